// round 2
// baseline (speedup 1.0000x reference)
#include <cuda_runtime.h>

// ---------------- problem constants ----------------
#define HWDIM 96
#define PIX   9216          // 96*96
#define NTOT  147456        // 16 * 9216
#define NG    1024          // groups per image (32*32)
#define BG    16384         // 16 * 1024
#define SCALE 0.17677669529663687f   // 32^-0.5

// ---------------- scratch (static device globals; no allocation) ----------------
__device__ float g_qkv[113246208];   // [gidx][768][9]  (453 MB)
__device__ float g_tok[768];         // qkv of the (shared) group token
__device__ float g_t[4194304];       // [b][256][1024]  LN+GELU'd group tokens
__device__ float g_gf[37748736];     // [(b*8+h)*1024 + g][9][32]
__device__ float g_wq[4194304];      // [(b*8+h)*1024 + n][32]
__device__ float g_wkt[4194304];     // [(b*8+h)*32 + d][1024]
__device__ float g_dots[134217728];  // [(b*8+h)][1024][1024]  (537 MB), softmaxed in-place
__device__ float g_agg[37748736];    // [(b*8+h)*1024 + i][9][32]

__device__ __forceinline__ float allsum(float v){
  #pragma unroll
  for (int o = 16; o > 0; o >>= 1) v += __shfl_xor_sync(0xffffffffu, v, o);
  return v;
}
__device__ __forceinline__ float allmax(float v){
  #pragma unroll
  for (int o = 16; o > 0; o >>= 1) v = fmaxf(v, __shfl_xor_sync(0xffffffffu, v, o));
  return v;
}

// ---------------- K0: qkv of the shared group token (768 dots of len 256) ----------------
__global__ void k_tok(const float* __restrict__ w, const float* __restrict__ tok){
  int o = blockIdx.x * 256 + threadIdx.x;
  if (o < 768){
    const float* wr = w + o * 256;
    float s = 0.f;
    #pragma unroll 8
    for (int c = 0; c < 256; c++) s += wr[c] * tok[c];
    g_tok[o] = s;
  }
}

// ---------------- K1: qkv GEMM  M=768, K=256, N=147456 ; scatter to group layout --------
__global__ __launch_bounds__(256) void k_qkv(const float* __restrict__ A,
                                             const float* __restrict__ X){
  __shared__ float As[8][128];     // [k][m]  (transposed)
  __shared__ float Bs[8][128];     // [k][n]
  int tid = threadIdx.x;
  int m0 = blockIdx.y * 128;
  int n0 = blockIdx.x * 128;
  int b = n0 / PIX;
  int pix0 = n0 - b * PIX;         // tile never crosses a batch image (9216 % 128 == 0)
  const float* Bp = X + (size_t)b * 256 * PIX + pix0;

  int arow = tid >> 1, acol = (tid & 1) * 4;
  int brow = tid >> 5, bcol = (tid & 31) * 4;
  int ty = tid >> 4, tx = tid & 15;

  float acc[8][8];
  #pragma unroll
  for (int i = 0; i < 8; i++)
    #pragma unroll
    for (int j = 0; j < 8; j++) acc[i][j] = 0.f;

  for (int k0 = 0; k0 < 256; k0 += 8){
    float4 av = *(const float4*)(A + (m0 + arow) * 256 + k0 + acol);
    As[acol + 0][arow] = av.x; As[acol + 1][arow] = av.y;
    As[acol + 2][arow] = av.z; As[acol + 3][arow] = av.w;
    float4 bv = *(const float4*)(Bp + (size_t)(k0 + brow) * PIX + bcol);
    *(float4*)&Bs[brow][bcol] = bv;
    __syncthreads();
    #pragma unroll
    for (int kk = 0; kk < 8; kk++){
      float4 a0 = *(const float4*)&As[kk][ty * 8];
      float4 a1 = *(const float4*)&As[kk][ty * 8 + 4];
      float4 b0 = *(const float4*)&Bs[kk][tx * 8];
      float4 b1 = *(const float4*)&Bs[kk][tx * 8 + 4];
      float ar[8] = {a0.x,a0.y,a0.z,a0.w,a1.x,a1.y,a1.z,a1.w};
      float br[8] = {b0.x,b0.y,b0.z,b0.w,b1.x,b1.y,b1.z,b1.w};
      #pragma unroll
      for (int i = 0; i < 8; i++)
        #pragma unroll
        for (int j = 0; j < 8; j++) acc[i][j] = fmaf(ar[i], br[j], acc[i][j]);
    }
    __syncthreads();
  }
  // scatter to group-major layout g_qkv[gidx][o][win]
  #pragma unroll
  for (int j = 0; j < 8; j++){
    int pix = pix0 + tx * 8 + j;
    int y = pix / HWDIM, xc = pix - y * HWDIM;
    int gidx = b * NG + (y / 3) * 32 + (xc / 3);
    int win = (y % 3) * 3 + (xc % 3);
    size_t base = (size_t)gidx * 6912 + win;
    #pragma unroll
    for (int i = 0; i < 8; i++){
      int o = m0 + ty * 8 + i;
      g_qkv[base + (size_t)o * 9] = acc[i][j];
    }
  }
}

// ---------------- K2: per-group 10-token attention + LN + GELU ----------------
__global__ __launch_bounds__(256) void k_attn1(const float* __restrict__ gamma,
                                               const float* __restrict__ beta){
  __shared__ float sq[6912];        // qkv of the 9 pixels: [o][win]
  __shared__ float stok[768];       // qkv of the token
  __shared__ float sd[8][10][10];   // per-head attention matrix
  int gidx = blockIdx.x;
  int b = gidx >> 10, g = gidx & 1023;
  int tid = threadIdx.x;

  const float4* src = (const float4*)(g_qkv + (size_t)gidx * 6912);
  for (int i = tid; i < 1728; i += 256) ((float4*)sq)[i] = src[i];
  for (int i = tid; i < 768; i += 256) stok[i] = g_tok[i];
  __syncthreads();

  int hh = tid >> 5, lane = tid & 31;
  int oq = hh * 32 + lane;

  float qr[10], kr[10], vr[10];
  qr[0] = stok[oq]; kr[0] = stok[oq + 256]; vr[0] = stok[oq + 512];
  #pragma unroll
  for (int n = 1; n < 10; n++){
    qr[n] = sq[oq * 9 + n - 1];
    kr[n] = sq[(oq + 256) * 9 + n - 1];
    vr[n] = sq[(oq + 512) * 9 + n - 1];
  }
  // dots[i][j] = SCALE * sum_d q*k  (lane = d, warp reduce)
  #pragma unroll
  for (int i = 0; i < 10; i++){
    #pragma unroll
    for (int j = 0; j < 10; j++){
      float t = allsum(qr[i] * kr[j]);
      if (lane == 0) sd[hh][i][j] = t * SCALE;
    }
  }
  __syncwarp();
  // softmax per row (lanes 0..9 each own a row)
  if (lane < 10){
    float row[10]; float m = -1e30f;
    #pragma unroll
    for (int j = 0; j < 10; j++){ row[j] = sd[hh][lane][j]; m = fmaxf(m, row[j]); }
    float s = 0.f;
    #pragma unroll
    for (int j = 0; j < 10; j++){ row[j] = __expf(row[j] - m); s += row[j]; }
    float inv = 1.f / s;
    #pragma unroll
    for (int j = 0; j < 10; j++) sd[hh][lane][j] = row[j] * inv;
  }
  __syncwarp();
  // out row 0 -> LayerNorm(d) + exact GELU -> g_t ; rows 1..9 -> g_gf
  float x0 = 0.f;
  #pragma unroll
  for (int j = 0; j < 10; j++) x0 = fmaf(sd[hh][0][j], vr[j], x0);
  float mu = allsum(x0) * 0.03125f;
  float dv = x0 - mu;
  float var = allsum(dv * dv) * 0.03125f;
  float xn = dv * rsqrtf(var + 1e-5f) * gamma[lane] + beta[lane];
  float ge = 0.5f * xn * (1.f + erff(xn * 0.70710678118654752f));
  g_t[b * 262144 + oq * 1024 + g] = ge;

  size_t gfb = ((size_t)(b * 8 + hh) * NG + g) * 288 + lane;
  #pragma unroll
  for (int i = 1; i < 10; i++){
    float o = 0.f;
    #pragma unroll
    for (int j = 0; j < 10; j++) o = fmaf(sd[hh][i][j], vr[j], o);
    g_gf[gfb + (i - 1) * 32] = o;
  }
}

// ---------------- K3: qk GEMM  per-batch M=512, K=256, N=1024  (+bias, split wq/wk) -----
__global__ __launch_bounds__(256) void k_qk(const float* __restrict__ A,
                                            const float* __restrict__ bias){
  __shared__ float As[16][64];
  __shared__ float Bs[16][64];
  int tid = threadIdx.x;
  int n0 = blockIdx.x * 64, m0 = blockIdx.y * 64, b = blockIdx.z;
  const float* Bp = g_t + b * 262144;
  int ty = tid >> 4, tx = tid & 15;
  int ar = tid >> 2, ac = (tid & 3) * 4;
  int br = tid >> 4, bc = (tid & 15) * 4;
  float acc[4][4];
  #pragma unroll
  for (int i = 0; i < 4; i++)
    #pragma unroll
    for (int j = 0; j < 4; j++) acc[i][j] = 0.f;

  for (int k0 = 0; k0 < 256; k0 += 16){
    float4 av = *(const float4*)(A + (m0 + ar) * 256 + k0 + ac);
    As[ac + 0][ar] = av.x; As[ac + 1][ar] = av.y;
    As[ac + 2][ar] = av.z; As[ac + 3][ar] = av.w;
    *(float4*)&Bs[br][bc] = *(const float4*)(Bp + (k0 + br) * 1024 + n0 + bc);
    __syncthreads();
    #pragma unroll
    for (int kk = 0; kk < 16; kk++){
      float4 a = *(const float4*)&As[kk][ty * 4];
      float4 bb = *(const float4*)&Bs[kk][tx * 4];
      float arr[4] = {a.x,a.y,a.z,a.w};
      float brr[4] = {bb.x,bb.y,bb.z,bb.w};
      #pragma unroll
      for (int i = 0; i < 4; i++)
        #pragma unroll
        for (int j = 0; j < 4; j++) acc[i][j] = fmaf(arr[i], brr[j], acc[i][j]);
    }
    __syncthreads();
  }
  #pragma unroll
  for (int i = 0; i < 4; i++){
    int o = m0 + ty * 4 + i;
    float bi = bias[o];
    int h = o >> 6, dd = o & 63;
    #pragma unroll
    for (int j = 0; j < 4; j++){
      int n = n0 + tx * 4 + j;
      float v = acc[i][j] + bi;
      if (dd < 32) g_wq[((b * 8 + h) * 1024 + n) * 32 + dd] = v;
      else         g_wkt[((b * 8 + h) * 32 + (dd - 32)) * 1024 + n] = v;
    }
  }
}

// ---------------- K4a: window dots  per (b,h): 1024x1024, K=32 ----------------
__global__ __launch_bounds__(256) void k_dots(){
  __shared__ float As[32][64];
  __shared__ float Bs[32][64];
  int tid = threadIdx.x;
  int bh = blockIdx.z;
  int m0 = blockIdx.y * 64, n0 = blockIdx.x * 64;
  const float* Ap = g_wq + bh * 32768;
  const float* Bp = g_wkt + bh * 32768;
  for (int l = tid; l < 512; l += 256){
    int r = l >> 3, c = (l & 7) * 4;
    float4 v = *(const float4*)(Ap + (m0 + r) * 32 + c);
    As[c + 0][r] = v.x; As[c + 1][r] = v.y; As[c + 2][r] = v.z; As[c + 3][r] = v.w;
  }
  for (int l = tid; l < 512; l += 256){
    int r = l >> 4, c = (l & 15) * 4;
    *(float4*)&Bs[r][c] = *(const float4*)(Bp + r * 1024 + n0 + c);
  }
  __syncthreads();
  int ty = tid >> 4, tx = tid & 15;
  float acc[4][4];
  #pragma unroll
  for (int i = 0; i < 4; i++)
    #pragma unroll
    for (int j = 0; j < 4; j++) acc[i][j] = 0.f;
  #pragma unroll
  for (int kk = 0; kk < 32; kk++){
    float4 a = *(const float4*)&As[kk][ty * 4];
    float4 bb = *(const float4*)&Bs[kk][tx * 4];
    float arr[4] = {a.x,a.y,a.z,a.w};
    float brr[4] = {bb.x,bb.y,bb.z,bb.w};
    #pragma unroll
    for (int i = 0; i < 4; i++)
      #pragma unroll
      for (int j = 0; j < 4; j++) acc[i][j] = fmaf(arr[i], brr[j], acc[i][j]);
  }
  float* out = g_dots + (size_t)bh * 1048576;
  #pragma unroll
  for (int i = 0; i < 4; i++){
    float4 v = make_float4(acc[i][0]*SCALE, acc[i][1]*SCALE, acc[i][2]*SCALE, acc[i][3]*SCALE);
    *(float4*)&out[(size_t)(m0 + ty * 4 + i) * 1024 + n0 + tx * 4] = v;
  }
}

// ---------------- K4b: softmax rows of g_dots in-place (warp per row) ----------------
__global__ __launch_bounds__(256) void k_soft(){
  int row = blockIdx.x * 8 + (threadIdx.x >> 5);
  int lane = threadIdx.x & 31;
  float* r = g_dots + (size_t)row * 1024;
  float v[32];
  #pragma unroll
  for (int e = 0; e < 32; e++) v[e] = r[lane + e * 32];
  float m = v[0];
  #pragma unroll
  for (int e = 1; e < 32; e++) m = fmaxf(m, v[e]);
  m = allmax(m);
  float s = 0.f;
  #pragma unroll
  for (int e = 0; e < 32; e++){ v[e] = __expf(v[e] - m); s += v[e]; }
  s = allsum(s);
  float inv = 1.f / s;
  #pragma unroll
  for (int e = 0; e < 32; e++) r[lane + e * 32] = v[e] * inv;
}

// ---------------- K4c: agg GEMM  per (b,h): M=1024, N=288, K=1024 ----------------
__global__ __launch_bounds__(256) void k_agg(){
  __shared__ float As[16][65];   // [k][m], padded
  __shared__ float Bs[16][96];   // [k][n]
  int tid = threadIdx.x;
  int bh = blockIdx.z;
  int m0 = blockIdx.y * 64, n0 = blockIdx.x * 96;
  const float* Ap = g_dots + (size_t)bh * 1048576 + (size_t)m0 * 1024;
  const float* Bp = g_gf + (size_t)bh * 294912 + n0;
  int ty = tid >> 4, tx = tid & 15;
  float acc[4][6];
  #pragma unroll
  for (int i = 0; i < 4; i++)
    #pragma unroll
    for (int j = 0; j < 6; j++) acc[i][j] = 0.f;

  for (int k0 = 0; k0 < 1024; k0 += 16){
    for (int l = tid; l < 1024; l += 256){
      int r = l >> 4, c = l & 15;
      As[c][r] = Ap[(size_t)r * 1024 + k0 + c];
    }
    for (int l = tid; l < 1536; l += 256){
      int r = l / 96, c = l - r * 96;
      Bs[r][c] = Bp[(size_t)(k0 + r) * 288 + c];
    }
    __syncthreads();
    #pragma unroll
    for (int kk = 0; kk < 16; kk++){
      float arr[4], brr[6];
      #pragma unroll
      for (int i = 0; i < 4; i++) arr[i] = As[kk][ty * 4 + i];
      #pragma unroll
      for (int j = 0; j < 6; j++) brr[j] = Bs[kk][tx * 6 + j];
      #pragma unroll
      for (int i = 0; i < 4; i++)
        #pragma unroll
        for (int j = 0; j < 6; j++) acc[i][j] = fmaf(arr[i], brr[j], acc[i][j]);
    }
    __syncthreads();
  }
  float* out = g_agg + (size_t)bh * 294912;
  #pragma unroll
  for (int i = 0; i < 4; i++)
    #pragma unroll
    for (int j = 0; j < 6; j++)
      out[(size_t)(m0 + ty * 4 + i) * 288 + n0 + tx * 6 + j] = acc[i][j];
}

// ---------------- K5: output projection  M=256, K=256, N=147456, gathers agg ------------
__global__ __launch_bounds__(256) void k_out(const float* __restrict__ W,
                                             const float* __restrict__ bias,
                                             float* __restrict__ out){
  __shared__ float As[64][33];   // [m][k], padded
  __shared__ float Bs[32][128];  // [k=d][n]
  int tid = threadIdx.x;
  int n0 = blockIdx.x * 128, m0 = blockIdx.y * 64;
  int b = n0 / PIX;
  int pix0 = n0 - b * PIX;
  int nb = tid & 127;
  int khalf = tid >> 7;
  int pix = pix0 + nb;
  int y = pix / HWDIM, xc = pix - y * HWDIM;
  int g = (y / 3) * 32 + xc / 3;
  int win = (y % 3) * 3 + (xc % 3);
  size_t colbase = (size_t)b * 2359296 + (size_t)g * 288 + win * 32 + khalf * 16;
  int ty = tid >> 4, tx = tid & 15;
  float acc[4][8];
  #pragma unroll
  for (int i = 0; i < 4; i++)
    #pragma unroll
    for (int j = 0; j < 8; j++) acc[i][j] = 0.f;

  for (int kt = 0; kt < 8; kt++){        // head = K tile of 32
    for (int l = tid; l < 2048; l += 256){
      int r = l >> 5, c = l & 31;
      As[r][c] = W[(m0 + r) * 256 + kt * 32 + c];
    }
    const float* bsrc = g_agg + colbase + (size_t)kt * 294912;
    float4 v0 = *(const float4*)(bsrc + 0);
    float4 v1 = *(const float4*)(bsrc + 4);
    float4 v2 = *(const float4*)(bsrc + 8);
    float4 v3 = *(const float4*)(bsrc + 12);
    int kb = khalf * 16;
    Bs[kb+0][nb]=v0.x; Bs[kb+1][nb]=v0.y; Bs[kb+2][nb]=v0.z; Bs[kb+3][nb]=v0.w;
    Bs[kb+4][nb]=v1.x; Bs[kb+5][nb]=v1.y; Bs[kb+6][nb]=v1.z; Bs[kb+7][nb]=v1.w;
    Bs[kb+8][nb]=v2.x; Bs[kb+9][nb]=v2.y; Bs[kb+10][nb]=v2.z; Bs[kb+11][nb]=v2.w;
    Bs[kb+12][nb]=v3.x; Bs[kb+13][nb]=v3.y; Bs[kb+14][nb]=v3.z; Bs[kb+15][nb]=v3.w;
    __syncthreads();
    #pragma unroll
    for (int kk = 0; kk < 32; kk++){
      float arr[4];
      #pragma unroll
      for (int i = 0; i < 4; i++) arr[i] = As[ty * 4 + i][kk];
      float4 b0 = *(const float4*)&Bs[kk][tx * 8];
      float4 b1 = *(const float4*)&Bs[kk][tx * 8 + 4];
      float brr[8] = {b0.x,b0.y,b0.z,b0.w,b1.x,b1.y,b1.z,b1.w};
      #pragma unroll
      for (int i = 0; i < 4; i++)
        #pragma unroll
        for (int j = 0; j < 8; j++) acc[i][j] = fmaf(arr[i], brr[j], acc[i][j]);
    }
    __syncthreads();
  }
  float* op = out + ((size_t)b * 256 + m0) * PIX + pix0;
  #pragma unroll
  for (int i = 0; i < 4; i++){
    int o = m0 + ty * 4 + i;
    float bi = bias[o];
    float4 w0 = make_float4(acc[i][0]+bi, acc[i][1]+bi, acc[i][2]+bi, acc[i][3]+bi);
    float4 w1 = make_float4(acc[i][4]+bi, acc[i][5]+bi, acc[i][6]+bi, acc[i][7]+bi);
    *(float4*)&op[(size_t)(ty * 4 + i) * PIX + tx * 8] = w0;
    *(float4*)&op[(size_t)(ty * 4 + i) * PIX + tx * 8 + 4] = w1;
  }
}

// ---------------- launch ----------------
extern "C" void kernel_launch(void* const* d_in, const int* in_sizes, int n_in,
                              void* d_out, int out_size){
  const float* x      = (const float*)d_in[0];
  const float* w_qkv  = (const float*)d_in[1];
  const float* gtok   = (const float*)d_in[2];
  const float* gamma  = (const float*)d_in[3];
  const float* beta   = (const float*)d_in[4];
  const float* w_qk   = (const float*)d_in[5];
  const float* b_qk   = (const float*)d_in[6];
  const float* w_out  = (const float*)d_in[7];
  const float* b_out  = (const float*)d_in[8];
  float* out = (float*)d_out;

  k_tok  <<<3, 256>>>(w_qkv, gtok);
  k_qkv  <<<dim3(1152, 6), 256>>>(w_qkv, x);
  k_attn1<<<16384, 256>>>(gamma, beta);
  k_qk   <<<dim3(16, 8, 16), 256>>>(w_qk, b_qk);
  k_dots <<<dim3(16, 16, 128), 256>>>();
  k_soft <<<16384, 256>>>();
  k_agg  <<<dim3(3, 16, 128), 256>>>();
  k_out  <<<dim3(1152, 4), 256>>>(w_out, b_out, out);
}

// round 3
// speedup vs baseline: 1.5196x; 1.5196x over previous
#include <cuda_runtime.h>
#include <cstdint>

// ---------------- problem constants ----------------
#define HWDIM 96
#define PIX   9216          // 96*96
#define NTOT  147456        // 16 * 9216
#define NG    1024          // groups per image (32*32)
#define BG    16384         // 16 * 1024
#define SCALE 0.17677669529663687f   // 32^-0.5

// ---------------- scratch (static device globals; no allocation) ----------------
__device__ float g_qkv[113246208];   // [gidx][768][9]  (453 MB)
__device__ float g_tok[768];         // qkv of the (shared) group token
__device__ float g_t[4194304];       // [b][256][1024]  LN+GELU'd group tokens
__device__ float g_gf[37748736];     // [(b*8+h)*1024 + g][9][32]
__device__ float g_wq[4194304];      // [(b*8+h)*1024 + n][32]
__device__ float g_wkt[4194304];     // [(b*8+h)*32 + d][1024]
__device__ float g_dots[134217728];  // [(b*8+h)][1024][1024]  softmaxed in-place
__device__ float g_agg[37748736];    // [(b*8+h)*1024 + i][9][32]

__device__ __forceinline__ float allsum(float v){
  #pragma unroll
  for (int o = 16; o > 0; o >>= 1) v += __shfl_xor_sync(0xffffffffu, v, o);
  return v;
}
__device__ __forceinline__ float allmax(float v){
  #pragma unroll
  for (int o = 16; o > 0; o >>= 1) v = fmaxf(v, __shfl_xor_sync(0xffffffffu, v, o));
  return v;
}
__device__ __forceinline__ uint32_t f2tf32(float v){
  uint32_t t;
  asm("cvt.rna.tf32.f32 %0, %1;" : "=r"(t) : "f"(v));
  return t;
}
__device__ __forceinline__ void mma_tf32(float* d, const uint32_t* a, const uint32_t* b){
  asm volatile(
    "mma.sync.aligned.m16n8k8.row.col.f32.tf32.tf32.f32 "
    "{%0,%1,%2,%3}, {%4,%5,%6,%7}, {%8,%9}, {%0,%1,%2,%3};\n"
    : "+f"(d[0]), "+f"(d[1]), "+f"(d[2]), "+f"(d[3])
    : "r"(a[0]), "r"(a[1]), "r"(a[2]), "r"(a[3]), "r"(b[0]), "r"(b[1]));
}

// ---------------- K0: qkv of the shared group token ----------------
__global__ void k_tok(const float* __restrict__ w, const float* __restrict__ tok){
  int o = blockIdx.x * 256 + threadIdx.x;
  if (o < 768){
    const float* wr = w + o * 256;
    float s = 0.f;
    #pragma unroll 8
    for (int c = 0; c < 256; c++) s += wr[c] * tok[c];
    g_tok[o] = s;
  }
}

// ---------------- K1: qkv GEMM (tf32 tensor cores)  M=768, K=256, N=147456 --------------
// block 128x128, 8 warps (4m x 2n), warp tile 32x64, k-step 16
__global__ __launch_bounds__(256) void k_qkv(const float* __restrict__ A,
                                             const float* __restrict__ X){
  __shared__ uint32_t As[16][132];   // [k][m] padded: bank = 4*(k%4)+m%8 -> conflict-free frags
  __shared__ uint32_t Bs[16][132];   // [k][n]
  int tid = threadIdx.x;
  int lane = tid & 31, warp = tid >> 5;
  int warpM = warp >> 1, warpN = warp & 1;
  int m0 = blockIdx.y * 128;
  int n0 = blockIdx.x * 128;
  int b = n0 / PIX;
  int pix0 = n0 - b * PIX;           // 9216 % 128 == 0 -> tile never crosses batch
  const float* Bp = X + (size_t)b * 256 * PIX + pix0;

  float acc[2][8][4];
  #pragma unroll
  for (int mt = 0; mt < 2; mt++)
    #pragma unroll
    for (int nt = 0; nt < 8; nt++)
      #pragma unroll
      for (int i = 0; i < 4; i++) acc[mt][nt][i] = 0.f;

  int ar = tid >> 1, ac = (tid & 1) * 8;       // A: row, k-col base
  int br = tid >> 4, bc = (tid & 15) * 8;      // B: k-row, col base

  for (int k0 = 0; k0 < 256; k0 += 16){
    float4 a0 = *(const float4*)(A + (m0 + ar) * 256 + k0 + ac);
    float4 a1 = *(const float4*)(A + (m0 + ar) * 256 + k0 + ac + 4);
    As[ac+0][ar]=f2tf32(a0.x); As[ac+1][ar]=f2tf32(a0.y);
    As[ac+2][ar]=f2tf32(a0.z); As[ac+3][ar]=f2tf32(a0.w);
    As[ac+4][ar]=f2tf32(a1.x); As[ac+5][ar]=f2tf32(a1.y);
    As[ac+6][ar]=f2tf32(a1.z); As[ac+7][ar]=f2tf32(a1.w);
    float4 b0 = *(const float4*)(Bp + (size_t)(k0 + br) * PIX + bc);
    float4 b1 = *(const float4*)(Bp + (size_t)(k0 + br) * PIX + bc + 4);
    Bs[br][bc+0]=f2tf32(b0.x); Bs[br][bc+1]=f2tf32(b0.y);
    Bs[br][bc+2]=f2tf32(b0.z); Bs[br][bc+3]=f2tf32(b0.w);
    Bs[br][bc+4]=f2tf32(b1.x); Bs[br][bc+5]=f2tf32(b1.y);
    Bs[br][bc+6]=f2tf32(b1.z); Bs[br][bc+7]=f2tf32(b1.w);
    __syncthreads();
    #pragma unroll
    for (int kk = 0; kk < 16; kk += 8){
      uint32_t af[2][4], bf[8][2];
      int kr = kk + (lane & 3);
      #pragma unroll
      for (int mt = 0; mt < 2; mt++){
        int rb = warpM * 32 + mt * 16 + (lane >> 2);
        af[mt][0] = As[kr    ][rb];
        af[mt][1] = As[kr    ][rb + 8];
        af[mt][2] = As[kr + 4][rb];
        af[mt][3] = As[kr + 4][rb + 8];
      }
      #pragma unroll
      for (int nt = 0; nt < 8; nt++){
        int nb = warpN * 64 + nt * 8 + (lane >> 2);
        bf[nt][0] = Bs[kr    ][nb];
        bf[nt][1] = Bs[kr + 4][nb];
      }
      #pragma unroll
      for (int mt = 0; mt < 2; mt++)
        #pragma unroll
        for (int nt = 0; nt < 8; nt++)
          mma_tf32(acc[mt][nt], af[mt], bf[nt]);
    }
    __syncthreads();
  }
  // scatter epilogue to g_qkv[gidx][o][win]
  #pragma unroll
  for (int nt = 0; nt < 8; nt++){
    #pragma unroll
    for (int jj = 0; jj < 2; jj++){
      int pix = pix0 + warpN * 64 + nt * 8 + (lane & 3) * 2 + jj;
      int y = pix / HWDIM, xc = pix - y * HWDIM;
      size_t base = ((size_t)(b * NG + (y / 3) * 32 + (xc / 3))) * 6912
                  + (y % 3) * 3 + (xc % 3);
      #pragma unroll
      for (int mt = 0; mt < 2; mt++){
        #pragma unroll
        for (int ii = 0; ii < 2; ii++){
          int o = m0 + warpM * 32 + mt * 16 + (lane >> 2) + ii * 8;
          g_qkv[base + (size_t)o * 9] = acc[mt][nt][ii * 2 + jj];
        }
      }
    }
  }
}

// ---------------- K2: per-group 10-token attention + LN + GELU ----------------
__global__ __launch_bounds__(256) void k_attn1(const float* __restrict__ gamma,
                                               const float* __restrict__ beta){
  __shared__ float sq[6912];
  __shared__ float stok[768];
  __shared__ float sd[8][10][10];
  int gidx = blockIdx.x;
  int b = gidx >> 10, g = gidx & 1023;
  int tid = threadIdx.x;

  const float4* src = (const float4*)(g_qkv + (size_t)gidx * 6912);
  for (int i = tid; i < 1728; i += 256) ((float4*)sq)[i] = src[i];
  for (int i = tid; i < 768; i += 256) stok[i] = g_tok[i];
  __syncthreads();

  int hh = tid >> 5, lane = tid & 31;
  int oq = hh * 32 + lane;

  float qr[10], kr[10], vr[10];
  qr[0] = stok[oq]; kr[0] = stok[oq + 256]; vr[0] = stok[oq + 512];
  #pragma unroll
  for (int n = 1; n < 10; n++){
    qr[n] = sq[oq * 9 + n - 1];
    kr[n] = sq[(oq + 256) * 9 + n - 1];
    vr[n] = sq[(oq + 512) * 9 + n - 1];
  }
  #pragma unroll
  for (int i = 0; i < 10; i++){
    #pragma unroll
    for (int j = 0; j < 10; j++){
      float t = allsum(qr[i] * kr[j]);
      if (lane == 0) sd[hh][i][j] = t * SCALE;
    }
  }
  __syncwarp();
  if (lane < 10){
    float row[10]; float m = -1e30f;
    #pragma unroll
    for (int j = 0; j < 10; j++){ row[j] = sd[hh][lane][j]; m = fmaxf(m, row[j]); }
    float s = 0.f;
    #pragma unroll
    for (int j = 0; j < 10; j++){ row[j] = __expf(row[j] - m); s += row[j]; }
    float inv = 1.f / s;
    #pragma unroll
    for (int j = 0; j < 10; j++) sd[hh][lane][j] = row[j] * inv;
  }
  __syncwarp();
  float x0 = 0.f;
  #pragma unroll
  for (int j = 0; j < 10; j++) x0 = fmaf(sd[hh][0][j], vr[j], x0);
  float mu = allsum(x0) * 0.03125f;
  float dv = x0 - mu;
  float var = allsum(dv * dv) * 0.03125f;
  float xn = dv * rsqrtf(var + 1e-5f) * gamma[lane] + beta[lane];
  float ge = 0.5f * xn * (1.f + erff(xn * 0.70710678118654752f));
  g_t[b * 262144 + oq * 1024 + g] = ge;

  size_t gfb = ((size_t)(b * 8 + hh) * NG + g) * 288 + lane;
  #pragma unroll
  for (int i = 1; i < 10; i++){
    float o = 0.f;
    #pragma unroll
    for (int j = 0; j < 10; j++) o = fmaf(sd[hh][i][j], vr[j], o);
    g_gf[gfb + (i - 1) * 32] = o;
  }
}

// ---------------- K3: qk GEMM per-batch M=512, K=256, N=1024 ----------------
__global__ __launch_bounds__(256) void k_qk(const float* __restrict__ A,
                                            const float* __restrict__ bias){
  __shared__ float As[16][64];
  __shared__ float Bs[16][64];
  int tid = threadIdx.x;
  int n0 = blockIdx.x * 64, m0 = blockIdx.y * 64, b = blockIdx.z;
  const float* Bp = g_t + b * 262144;
  int ty = tid >> 4, tx = tid & 15;
  int ar = tid >> 2, ac = (tid & 3) * 4;
  int br = tid >> 4, bc = (tid & 15) * 4;
  float acc[4][4];
  #pragma unroll
  for (int i = 0; i < 4; i++)
    #pragma unroll
    for (int j = 0; j < 4; j++) acc[i][j] = 0.f;

  for (int k0 = 0; k0 < 256; k0 += 16){
    float4 av = *(const float4*)(A + (m0 + ar) * 256 + k0 + ac);
    As[ac + 0][ar] = av.x; As[ac + 1][ar] = av.y;
    As[ac + 2][ar] = av.z; As[ac + 3][ar] = av.w;
    *(float4*)&Bs[br][bc] = *(const float4*)(Bp + (k0 + br) * 1024 + n0 + bc);
    __syncthreads();
    #pragma unroll
    for (int kk = 0; kk < 16; kk++){
      float4 a = *(const float4*)&As[kk][ty * 4];
      float4 bb = *(const float4*)&Bs[kk][tx * 4];
      float arr[4] = {a.x,a.y,a.z,a.w};
      float brr[4] = {bb.x,bb.y,bb.z,bb.w};
      #pragma unroll
      for (int i = 0; i < 4; i++)
        #pragma unroll
        for (int j = 0; j < 4; j++) acc[i][j] = fmaf(arr[i], brr[j], acc[i][j]);
    }
    __syncthreads();
  }
  #pragma unroll
  for (int i = 0; i < 4; i++){
    int o = m0 + ty * 4 + i;
    float bi = bias[o];
    int h = o >> 6, dd = o & 63;
    #pragma unroll
    for (int j = 0; j < 4; j++){
      int n = n0 + tx * 4 + j;
      float v = acc[i][j] + bi;
      if (dd < 32) g_wq[((b * 8 + h) * 1024 + n) * 32 + dd] = v;
      else         g_wkt[((b * 8 + h) * 32 + (dd - 32)) * 1024 + n] = v;
    }
  }
}

// ---------------- K4a: window dots per (b,h): 1024x1024, K=32 ----------------
__global__ __launch_bounds__(256) void k_dots(){
  __shared__ float As[32][64];
  __shared__ float Bs[32][64];
  int tid = threadIdx.x;
  int bh = blockIdx.z;
  int m0 = blockIdx.y * 64, n0 = blockIdx.x * 64;
  const float* Ap = g_wq + bh * 32768;
  const float* Bp = g_wkt + bh * 32768;
  for (int l = tid; l < 512; l += 256){
    int r = l >> 3, c = (l & 7) * 4;
    float4 v = *(const float4*)(Ap + (m0 + r) * 32 + c);
    As[c + 0][r] = v.x; As[c + 1][r] = v.y; As[c + 2][r] = v.z; As[c + 3][r] = v.w;
  }
  for (int l = tid; l < 512; l += 256){
    int r = l >> 4, c = (l & 15) * 4;
    *(float4*)&Bs[r][c] = *(const float4*)(Bp + r * 1024 + n0 + c);
  }
  __syncthreads();
  int ty = tid >> 4, tx = tid & 15;
  float acc[4][4];
  #pragma unroll
  for (int i = 0; i < 4; i++)
    #pragma unroll
    for (int j = 0; j < 4; j++) acc[i][j] = 0.f;
  #pragma unroll
  for (int kk = 0; kk < 32; kk++){
    float4 a = *(const float4*)&As[kk][ty * 4];
    float4 bb = *(const float4*)&Bs[kk][tx * 4];
    float arr[4] = {a.x,a.y,a.z,a.w};
    float brr[4] = {bb.x,bb.y,bb.z,bb.w};
    #pragma unroll
    for (int i = 0; i < 4; i++)
      #pragma unroll
      for (int j = 0; j < 4; j++) acc[i][j] = fmaf(arr[i], brr[j], acc[i][j]);
  }
  float* out = g_dots + (size_t)bh * 1048576;
  #pragma unroll
  for (int i = 0; i < 4; i++){
    float4 v = make_float4(acc[i][0]*SCALE, acc[i][1]*SCALE, acc[i][2]*SCALE, acc[i][3]*SCALE);
    *(float4*)&out[(size_t)(m0 + ty * 4 + i) * 1024 + n0 + tx * 4] = v;
  }
}

// ---------------- K4b: softmax rows of g_dots in-place ----------------
__global__ __launch_bounds__(256) void k_soft(){
  int row = blockIdx.x * 8 + (threadIdx.x >> 5);
  int lane = threadIdx.x & 31;
  float* r = g_dots + (size_t)row * 1024;
  float v[32];
  #pragma unroll
  for (int e = 0; e < 32; e++) v[e] = r[lane + e * 32];
  float m = v[0];
  #pragma unroll
  for (int e = 1; e < 32; e++) m = fmaxf(m, v[e]);
  m = allmax(m);
  float s = 0.f;
  #pragma unroll
  for (int e = 0; e < 32; e++){ v[e] = __expf(v[e] - m); s += v[e]; }
  s = allsum(s);
  float inv = 1.f / s;
  #pragma unroll
  for (int e = 0; e < 32; e++) r[lane + e * 32] = v[e] * inv;
}

// ---------------- K4c: agg GEMM (tf32 tensor cores) per (b,h): M=1024,N=288,K=1024 ------
// block 128x96, 8 warps (4m x 2n), warp tile 32x48, k-step 16
__global__ __launch_bounds__(256) void k_agg(){
  __shared__ uint32_t As[16][132];   // [k][m]
  __shared__ uint32_t Bs[16][100];   // [k][n]
  int tid = threadIdx.x;
  int lane = tid & 31, warp = tid >> 5;
  int warpM = warp >> 1, warpN = warp & 1;
  int bh = blockIdx.z;
  int m0 = blockIdx.y * 128, n0 = blockIdx.x * 96;
  const float* Ap = g_dots + (size_t)bh * 1048576;
  const float* Bp = g_gf + (size_t)bh * 294912 + n0;

  float acc[2][6][4];
  #pragma unroll
  for (int mt = 0; mt < 2; mt++)
    #pragma unroll
    for (int nt = 0; nt < 6; nt++)
      #pragma unroll
      for (int i = 0; i < 4; i++) acc[mt][nt][i] = 0.f;

  int ar = tid >> 1, ac = (tid & 1) * 8;

  for (int k0 = 0; k0 < 1024; k0 += 16){
    float4 a0 = *(const float4*)(Ap + (size_t)(m0 + ar) * 1024 + k0 + ac);
    float4 a1 = *(const float4*)(Ap + (size_t)(m0 + ar) * 1024 + k0 + ac + 4);
    As[ac+0][ar]=f2tf32(a0.x); As[ac+1][ar]=f2tf32(a0.y);
    As[ac+2][ar]=f2tf32(a0.z); As[ac+3][ar]=f2tf32(a0.w);
    As[ac+4][ar]=f2tf32(a1.x); As[ac+5][ar]=f2tf32(a1.y);
    As[ac+6][ar]=f2tf32(a1.z); As[ac+7][ar]=f2tf32(a1.w);
    for (int l = tid; l < 1536; l += 256){
      int r = l / 96, c = l - r * 96;
      Bs[r][c] = f2tf32(Bp[(size_t)(k0 + r) * 288 + c]);
    }
    __syncthreads();
    #pragma unroll
    for (int kk = 0; kk < 16; kk += 8){
      uint32_t af[2][4], bf[6][2];
      int kr = kk + (lane & 3);
      #pragma unroll
      for (int mt = 0; mt < 2; mt++){
        int rb = warpM * 32 + mt * 16 + (lane >> 2);
        af[mt][0] = As[kr    ][rb];
        af[mt][1] = As[kr    ][rb + 8];
        af[mt][2] = As[kr + 4][rb];
        af[mt][3] = As[kr + 4][rb + 8];
      }
      #pragma unroll
      for (int nt = 0; nt < 6; nt++){
        int nb = warpN * 48 + nt * 8 + (lane >> 2);
        bf[nt][0] = Bs[kr    ][nb];
        bf[nt][1] = Bs[kr + 4][nb];
      }
      #pragma unroll
      for (int mt = 0; mt < 2; mt++)
        #pragma unroll
        for (int nt = 0; nt < 6; nt++)
          mma_tf32(acc[mt][nt], af[mt], bf[nt]);
    }
    __syncthreads();
  }
  float* out = g_agg + (size_t)bh * 294912;
  #pragma unroll
  for (int mt = 0; mt < 2; mt++){
    #pragma unroll
    for (int nt = 0; nt < 6; nt++){
      #pragma unroll
      for (int ii = 0; ii < 2; ii++){
        int row = m0 + warpM * 32 + mt * 16 + (lane >> 2) + ii * 8;
        int col = n0 + warpN * 48 + nt * 8 + (lane & 3) * 2;
        out[(size_t)row * 288 + col    ] = acc[mt][nt][ii * 2];
        out[(size_t)row * 288 + col + 1] = acc[mt][nt][ii * 2 + 1];
      }
    }
  }
}

// ---------------- K5: output projection M=256, K=256, N=147456, gathers agg -------------
__global__ __launch_bounds__(256) void k_out(const float* __restrict__ W,
                                             const float* __restrict__ bias,
                                             float* __restrict__ out){
  __shared__ float As[64][33];
  __shared__ float Bs[32][128];
  int tid = threadIdx.x;
  int n0 = blockIdx.x * 128, m0 = blockIdx.y * 64;
  int b = n0 / PIX;
  int pix0 = n0 - b * PIX;
  int nb = tid & 127;
  int khalf = tid >> 7;
  int pix = pix0 + nb;
  int y = pix / HWDIM, xc = pix - y * HWDIM;
  int g = (y / 3) * 32 + xc / 3;
  int win = (y % 3) * 3 + (xc % 3);
  size_t colbase = (size_t)b * 2359296 + (size_t)g * 288 + win * 32 + khalf * 16;
  int ty = tid >> 4, tx = tid & 15;
  float acc[4][8];
  #pragma unroll
  for (int i = 0; i < 4; i++)
    #pragma unroll
    for (int j = 0; j < 8; j++) acc[i][j] = 0.f;

  for (int kt = 0; kt < 8; kt++){
    for (int l = tid; l < 2048; l += 256){
      int r = l >> 5, c = l & 31;
      As[r][c] = W[(m0 + r) * 256 + kt * 32 + c];
    }
    const float* bsrc = g_agg + colbase + (size_t)kt * 294912;
    float4 v0 = *(const float4*)(bsrc + 0);
    float4 v1 = *(const float4*)(bsrc + 4);
    float4 v2 = *(const float4*)(bsrc + 8);
    float4 v3 = *(const float4*)(bsrc + 12);
    int kb = khalf * 16;
    Bs[kb+0][nb]=v0.x; Bs[kb+1][nb]=v0.y; Bs[kb+2][nb]=v0.z; Bs[kb+3][nb]=v0.w;
    Bs[kb+4][nb]=v1.x; Bs[kb+5][nb]=v1.y; Bs[kb+6][nb]=v1.z; Bs[kb+7][nb]=v1.w;
    Bs[kb+8][nb]=v2.x; Bs[kb+9][nb]=v2.y; Bs[kb+10][nb]=v2.z; Bs[kb+11][nb]=v2.w;
    Bs[kb+12][nb]=v3.x; Bs[kb+13][nb]=v3.y; Bs[kb+14][nb]=v3.z; Bs[kb+15][nb]=v3.w;
    __syncthreads();
    #pragma unroll
    for (int kk = 0; kk < 32; kk++){
      float arr[4];
      #pragma unroll
      for (int i = 0; i < 4; i++) arr[i] = As[ty * 4 + i][kk];
      float4 b0 = *(const float4*)&Bs[kk][tx * 8];
      float4 b1 = *(const float4*)&Bs[kk][tx * 8 + 4];
      float brr[8] = {b0.x,b0.y,b0.z,b0.w,b1.x,b1.y,b1.z,b1.w};
      #pragma unroll
      for (int i = 0; i < 4; i++)
        #pragma unroll
        for (int j = 0; j < 8; j++) acc[i][j] = fmaf(arr[i], brr[j], acc[i][j]);
    }
    __syncthreads();
  }
  float* op = out + ((size_t)b * 256 + m0) * PIX + pix0;
  #pragma unroll
  for (int i = 0; i < 4; i++){
    int o = m0 + ty * 4 + i;
    float bi = bias[o];
    float4 w0 = make_float4(acc[i][0]+bi, acc[i][1]+bi, acc[i][2]+bi, acc[i][3]+bi);
    float4 w1 = make_float4(acc[i][4]+bi, acc[i][5]+bi, acc[i][6]+bi, acc[i][7]+bi);
    *(float4*)&op[(size_t)(ty * 4 + i) * PIX + tx * 8] = w0;
    *(float4*)&op[(size_t)(ty * 4 + i) * PIX + tx * 8 + 4] = w1;
  }
}

// ---------------- launch ----------------
extern "C" void kernel_launch(void* const* d_in, const int* in_sizes, int n_in,
                              void* d_out, int out_size){
  const float* x      = (const float*)d_in[0];
  const float* w_qkv  = (const float*)d_in[1];
  const float* gtok   = (const float*)d_in[2];
  const float* gamma  = (const float*)d_in[3];
  const float* beta   = (const float*)d_in[4];
  const float* w_qk   = (const float*)d_in[5];
  const float* b_qk   = (const float*)d_in[6];
  const float* w_out  = (const float*)d_in[7];
  const float* b_out  = (const float*)d_in[8];
  float* out = (float*)d_out;

  k_tok  <<<3, 256>>>(w_qkv, gtok);
  k_qkv  <<<dim3(1152, 6), 256>>>(w_qkv, x);
  k_attn1<<<16384, 256>>>(gamma, beta);
  k_qk   <<<dim3(16, 8, 16), 256>>>(w_qk, b_qk);
  k_dots <<<dim3(16, 16, 128), 256>>>();
  k_soft <<<16384, 256>>>();
  k_agg  <<<dim3(3, 8, 128), 256>>>();
  k_out  <<<dim3(1152, 4), 256>>>(w_out, b_out, out);
}

// round 4
// speedup vs baseline: 1.7661x; 1.1623x over previous
#include <cuda_runtime.h>
#include <cstdint>

// ---------------- problem constants ----------------
#define HWDIM 96
#define PIX   9216          // 96*96
#define NG    1024          // groups per image (32*32)
#define SCALE 0.17677669529663687f   // 32^-0.5

// ---------------- scratch (static device globals; no allocation) ----------------
__device__ float g_qkv[113246208];   // [gidx][768][9]
__device__ float g_tok[768];
__device__ float g_t[4194304];       // [b][256][1024]
__device__ float g_gf[37748736];     // [(b*8+h)*1024 + g][9][32]
__device__ float g_wq[4194304];      // [(b*8+h)*1024 + n][32]
__device__ float g_wkt[4194304];     // [(b*8+h)*32 + d][1024]
__device__ float g_dots[134217728];  // [(b*8+h)][1024][1024]
__device__ float g_agg[37748736];    // [(b*8+h)*1024 + i][9][32]

__device__ __forceinline__ float allsum(float v){
  #pragma unroll
  for (int o = 16; o > 0; o >>= 1) v += __shfl_xor_sync(0xffffffffu, v, o);
  return v;
}
__device__ __forceinline__ float allmax(float v){
  #pragma unroll
  for (int o = 16; o > 0; o >>= 1) v = fmaxf(v, __shfl_xor_sync(0xffffffffu, v, o));
  return v;
}
__device__ __forceinline__ uint32_t f2tf32(float v){
  uint32_t t;
  asm("cvt.rna.tf32.f32 %0, %1;" : "=r"(t) : "f"(v));
  return t;
}
__device__ __forceinline__ void mma_tf32(float* d, const uint32_t* a, const uint32_t* b){
  asm volatile(
    "mma.sync.aligned.m16n8k8.row.col.f32.tf32.tf32.f32 "
    "{%0,%1,%2,%3}, {%4,%5,%6,%7}, {%8,%9}, {%0,%1,%2,%3};\n"
    : "+f"(d[0]), "+f"(d[1]), "+f"(d[2]), "+f"(d[3])
    : "r"(a[0]), "r"(a[1]), "r"(a[2]), "r"(a[3]), "r"(b[0]), "r"(b[1]));
}

// ---------------- K0: qkv of the shared group token ----------------
__global__ void k_tok(const float* __restrict__ w, const float* __restrict__ tok){
  int o = blockIdx.x * 256 + threadIdx.x;
  if (o < 768){
    const float* wr = w + o * 256;
    float s = 0.f;
    #pragma unroll 8
    for (int c = 0; c < 256; c++) s += wr[c] * tok[c];
    g_tok[o] = s;
  }
}

// ---------------- K1: qkv GEMM (tf32)  M=768, K=256, N=147456 --------------
__global__ __launch_bounds__(256) void k_qkv(const float* __restrict__ A,
                                             const float* __restrict__ X){
  __shared__ uint32_t As[16][132];
  __shared__ uint32_t Bs[16][132];
  int tid = threadIdx.x;
  int lane = tid & 31, warp = tid >> 5;
  int warpM = warp >> 1, warpN = warp & 1;
  int m0 = blockIdx.y * 128;
  int n0 = blockIdx.x * 128;
  int b = n0 / PIX;
  int pix0 = n0 - b * PIX;
  const float* Bp = X + (size_t)b * 256 * PIX + pix0;

  float acc[2][8][4];
  #pragma unroll
  for (int mt = 0; mt < 2; mt++)
    #pragma unroll
    for (int nt = 0; nt < 8; nt++)
      #pragma unroll
      for (int i = 0; i < 4; i++) acc[mt][nt][i] = 0.f;

  int ar = tid >> 1, ac = (tid & 1) * 8;
  int br = tid >> 4, bc = (tid & 15) * 8;

  for (int k0 = 0; k0 < 256; k0 += 16){
    float4 a0 = *(const float4*)(A + (m0 + ar) * 256 + k0 + ac);
    float4 a1 = *(const float4*)(A + (m0 + ar) * 256 + k0 + ac + 4);
    As[ac+0][ar]=f2tf32(a0.x); As[ac+1][ar]=f2tf32(a0.y);
    As[ac+2][ar]=f2tf32(a0.z); As[ac+3][ar]=f2tf32(a0.w);
    As[ac+4][ar]=f2tf32(a1.x); As[ac+5][ar]=f2tf32(a1.y);
    As[ac+6][ar]=f2tf32(a1.z); As[ac+7][ar]=f2tf32(a1.w);
    float4 b0 = *(const float4*)(Bp + (size_t)(k0 + br) * PIX + bc);
    float4 b1 = *(const float4*)(Bp + (size_t)(k0 + br) * PIX + bc + 4);
    Bs[br][bc+0]=f2tf32(b0.x); Bs[br][bc+1]=f2tf32(b0.y);
    Bs[br][bc+2]=f2tf32(b0.z); Bs[br][bc+3]=f2tf32(b0.w);
    Bs[br][bc+4]=f2tf32(b1.x); Bs[br][bc+5]=f2tf32(b1.y);
    Bs[br][bc+6]=f2tf32(b1.z); Bs[br][bc+7]=f2tf32(b1.w);
    __syncthreads();
    #pragma unroll
    for (int kk = 0; kk < 16; kk += 8){
      uint32_t af[2][4], bf[8][2];
      int kr = kk + (lane & 3);
      #pragma unroll
      for (int mt = 0; mt < 2; mt++){
        int rb = warpM * 32 + mt * 16 + (lane >> 2);
        af[mt][0] = As[kr    ][rb];
        af[mt][1] = As[kr    ][rb + 8];
        af[mt][2] = As[kr + 4][rb];
        af[mt][3] = As[kr + 4][rb + 8];
      }
      #pragma unroll
      for (int nt = 0; nt < 8; nt++){
        int nb = warpN * 64 + nt * 8 + (lane >> 2);
        bf[nt][0] = Bs[kr    ][nb];
        bf[nt][1] = Bs[kr + 4][nb];
      }
      #pragma unroll
      for (int mt = 0; mt < 2; mt++)
        #pragma unroll
        for (int nt = 0; nt < 8; nt++)
          mma_tf32(acc[mt][nt], af[mt], bf[nt]);
    }
    __syncthreads();
  }
  #pragma unroll
  for (int nt = 0; nt < 8; nt++){
    #pragma unroll
    for (int jj = 0; jj < 2; jj++){
      int pix = pix0 + warpN * 64 + nt * 8 + (lane & 3) * 2 + jj;
      int y = pix / HWDIM, xc = pix - y * HWDIM;
      size_t base = ((size_t)(b * NG + (y / 3) * 32 + (xc / 3))) * 6912
                  + (y % 3) * 3 + (xc % 3);
      #pragma unroll
      for (int mt = 0; mt < 2; mt++){
        #pragma unroll
        for (int ii = 0; ii < 2; ii++){
          int o = m0 + warpM * 32 + mt * 16 + (lane >> 2) + ii * 8;
          g_qkv[base + (size_t)o * 9] = acc[mt][nt][ii * 2 + jj];
        }
      }
    }
  }
}

// ---------------- K2: per-group 10-token attention + LN + GELU ----------------
__global__ __launch_bounds__(256) void k_attn1(const float* __restrict__ gamma,
                                               const float* __restrict__ beta){
  __shared__ float sq[6912];
  __shared__ float stok[768];
  __shared__ float sd[8][10][10];
  int gidx = blockIdx.x;
  int b = gidx >> 10, g = gidx & 1023;
  int tid = threadIdx.x;

  const float4* src = (const float4*)(g_qkv + (size_t)gidx * 6912);
  for (int i = tid; i < 1728; i += 256) ((float4*)sq)[i] = src[i];
  for (int i = tid; i < 768; i += 256) stok[i] = g_tok[i];
  __syncthreads();

  int hh = tid >> 5, lane = tid & 31;
  int oq = hh * 32 + lane;

  float qr[10], kr[10], vr[10];
  qr[0] = stok[oq]; kr[0] = stok[oq + 256]; vr[0] = stok[oq + 512];
  #pragma unroll
  for (int n = 1; n < 10; n++){
    qr[n] = sq[oq * 9 + n - 1];
    kr[n] = sq[(oq + 256) * 9 + n - 1];
    vr[n] = sq[(oq + 512) * 9 + n - 1];
  }
  #pragma unroll
  for (int i = 0; i < 10; i++){
    #pragma unroll
    for (int j = 0; j < 10; j++){
      float t = allsum(qr[i] * kr[j]);
      if (lane == 0) sd[hh][i][j] = t * SCALE;
    }
  }
  __syncwarp();
  if (lane < 10){
    float row[10]; float m = -1e30f;
    #pragma unroll
    for (int j = 0; j < 10; j++){ row[j] = sd[hh][lane][j]; m = fmaxf(m, row[j]); }
    float s = 0.f;
    #pragma unroll
    for (int j = 0; j < 10; j++){ row[j] = __expf(row[j] - m); s += row[j]; }
    float inv = 1.f / s;
    #pragma unroll
    for (int j = 0; j < 10; j++) sd[hh][lane][j] = row[j] * inv;
  }
  __syncwarp();
  float x0 = 0.f;
  #pragma unroll
  for (int j = 0; j < 10; j++) x0 = fmaf(sd[hh][0][j], vr[j], x0);
  float mu = allsum(x0) * 0.03125f;
  float dv = x0 - mu;
  float var = allsum(dv * dv) * 0.03125f;
  float xn = dv * rsqrtf(var + 1e-5f) * gamma[lane] + beta[lane];
  float ge = 0.5f * xn * (1.f + erff(xn * 0.70710678118654752f));
  g_t[b * 262144 + oq * 1024 + g] = ge;

  size_t gfb = ((size_t)(b * 8 + hh) * NG + g) * 288 + lane;
  #pragma unroll
  for (int i = 1; i < 10; i++){
    float o = 0.f;
    #pragma unroll
    for (int j = 0; j < 10; j++) o = fmaf(sd[hh][i][j], vr[j], o);
    g_gf[gfb + (i - 1) * 32] = o;
  }
}

// ---------------- K3: qk GEMM (tf32) per-batch M=512, K=256, N=1024 ----------------
// block 128x128, grid (8, 4, 16)
__global__ __launch_bounds__(256) void k_qk(const float* __restrict__ A,
                                            const float* __restrict__ bias){
  __shared__ uint32_t As[16][132];
  __shared__ uint32_t Bs[16][132];
  int tid = threadIdx.x;
  int lane = tid & 31, warp = tid >> 5;
  int warpM = warp >> 1, warpN = warp & 1;
  int n0 = blockIdx.x * 128, m0 = blockIdx.y * 128, b = blockIdx.z;
  const float* Bp = g_t + b * 262144;

  float acc[2][8][4];
  #pragma unroll
  for (int mt = 0; mt < 2; mt++)
    #pragma unroll
    for (int nt = 0; nt < 8; nt++)
      #pragma unroll
      for (int i = 0; i < 4; i++) acc[mt][nt][i] = 0.f;

  int ar = tid >> 1, ac = (tid & 1) * 8;
  int br = tid >> 4, bc = (tid & 15) * 8;

  for (int k0 = 0; k0 < 256; k0 += 16){
    float4 a0 = *(const float4*)(A + (m0 + ar) * 256 + k0 + ac);
    float4 a1 = *(const float4*)(A + (m0 + ar) * 256 + k0 + ac + 4);
    As[ac+0][ar]=f2tf32(a0.x); As[ac+1][ar]=f2tf32(a0.y);
    As[ac+2][ar]=f2tf32(a0.z); As[ac+3][ar]=f2tf32(a0.w);
    As[ac+4][ar]=f2tf32(a1.x); As[ac+5][ar]=f2tf32(a1.y);
    As[ac+6][ar]=f2tf32(a1.z); As[ac+7][ar]=f2tf32(a1.w);
    float4 b0 = *(const float4*)(Bp + (k0 + br) * 1024 + n0 + bc);
    float4 b1 = *(const float4*)(Bp + (k0 + br) * 1024 + n0 + bc + 4);
    Bs[br][bc+0]=f2tf32(b0.x); Bs[br][bc+1]=f2tf32(b0.y);
    Bs[br][bc+2]=f2tf32(b0.z); Bs[br][bc+3]=f2tf32(b0.w);
    Bs[br][bc+4]=f2tf32(b1.x); Bs[br][bc+5]=f2tf32(b1.y);
    Bs[br][bc+6]=f2tf32(b1.z); Bs[br][bc+7]=f2tf32(b1.w);
    __syncthreads();
    #pragma unroll
    for (int kk = 0; kk < 16; kk += 8){
      uint32_t af[2][4], bf[8][2];
      int kr = kk + (lane & 3);
      #pragma unroll
      for (int mt = 0; mt < 2; mt++){
        int rb = warpM * 32 + mt * 16 + (lane >> 2);
        af[mt][0] = As[kr    ][rb];
        af[mt][1] = As[kr    ][rb + 8];
        af[mt][2] = As[kr + 4][rb];
        af[mt][3] = As[kr + 4][rb + 8];
      }
      #pragma unroll
      for (int nt = 0; nt < 8; nt++){
        int nb = warpN * 64 + nt * 8 + (lane >> 2);
        bf[nt][0] = Bs[kr    ][nb];
        bf[nt][1] = Bs[kr + 4][nb];
      }
      #pragma unroll
      for (int mt = 0; mt < 2; mt++)
        #pragma unroll
        for (int nt = 0; nt < 8; nt++)
          mma_tf32(acc[mt][nt], af[mt], bf[nt]);
    }
    __syncthreads();
  }
  // epilogue: +bias, split into g_wq / g_wkt
  #pragma unroll
  for (int mt = 0; mt < 2; mt++){
    #pragma unroll
    for (int ii = 0; ii < 2; ii++){
      int o = m0 + warpM * 32 + mt * 16 + (lane >> 2) + ii * 8;
      float bi = bias[o];
      int h = o >> 6, dd = o & 63;
      #pragma unroll
      for (int nt = 0; nt < 8; nt++){
        #pragma unroll
        for (int jj = 0; jj < 2; jj++){
          int n = n0 + warpN * 64 + nt * 8 + (lane & 3) * 2 + jj;
          float v = acc[mt][nt][ii * 2 + jj] + bi;
          if (dd < 32) g_wq[((b * 8 + h) * 1024 + n) * 32 + dd] = v;
          else         g_wkt[((b * 8 + h) * 32 + (dd - 32)) * 1024 + n] = v;
        }
      }
    }
  }
}

// ---------------- K4a: window dots (tf32) per (b,h): M=1024, N=1024, K=32 ---------------
// block 128x128, grid (8, 8, 128)
__global__ __launch_bounds__(256) void k_dots(){
  __shared__ uint32_t As[32][132];
  __shared__ uint32_t Bs[32][132];
  int tid = threadIdx.x;
  int lane = tid & 31, warp = tid >> 5;
  int warpM = warp >> 1, warpN = warp & 1;
  int bh = blockIdx.z;
  int m0 = blockIdx.y * 128, n0 = blockIdx.x * 128;
  const float* Ap = g_wq + bh * 32768;    // [1024][32]
  const float* Bp = g_wkt + bh * 32768;   // [32][1024]

  int ar = tid >> 1, ac = (tid & 1) * 16;
  #pragma unroll
  for (int i = 0; i < 16; i += 4){
    float4 v = *(const float4*)(Ap + (m0 + ar) * 32 + ac + i);
    As[ac+i+0][ar]=f2tf32(v.x); As[ac+i+1][ar]=f2tf32(v.y);
    As[ac+i+2][ar]=f2tf32(v.z); As[ac+i+3][ar]=f2tf32(v.w);
  }
  int br = tid >> 3, bc = (tid & 7) * 16;
  #pragma unroll
  for (int i = 0; i < 16; i += 4){
    float4 v = *(const float4*)(Bp + br * 1024 + n0 + bc + i);
    Bs[br][bc+i+0]=f2tf32(v.x); Bs[br][bc+i+1]=f2tf32(v.y);
    Bs[br][bc+i+2]=f2tf32(v.z); Bs[br][bc+i+3]=f2tf32(v.w);
  }
  __syncthreads();

  float acc[2][8][4];
  #pragma unroll
  for (int mt = 0; mt < 2; mt++)
    #pragma unroll
    for (int nt = 0; nt < 8; nt++)
      #pragma unroll
      for (int i = 0; i < 4; i++) acc[mt][nt][i] = 0.f;

  #pragma unroll
  for (int kk = 0; kk < 32; kk += 8){
    uint32_t af[2][4], bf[8][2];
    int kr = kk + (lane & 3);
    #pragma unroll
    for (int mt = 0; mt < 2; mt++){
      int rb = warpM * 32 + mt * 16 + (lane >> 2);
      af[mt][0] = As[kr    ][rb];
      af[mt][1] = As[kr    ][rb + 8];
      af[mt][2] = As[kr + 4][rb];
      af[mt][3] = As[kr + 4][rb + 8];
    }
    #pragma unroll
    for (int nt = 0; nt < 8; nt++){
      int nb = warpN * 64 + nt * 8 + (lane >> 2);
      bf[nt][0] = Bs[kr    ][nb];
      bf[nt][1] = Bs[kr + 4][nb];
    }
    #pragma unroll
    for (int mt = 0; mt < 2; mt++)
      #pragma unroll
      for (int nt = 0; nt < 8; nt++)
        mma_tf32(acc[mt][nt], af[mt], bf[nt]);
  }
  float* out = g_dots + (size_t)bh * 1048576;
  #pragma unroll
  for (int mt = 0; mt < 2; mt++){
    #pragma unroll
    for (int ii = 0; ii < 2; ii++){
      int row = m0 + warpM * 32 + mt * 16 + (lane >> 2) + ii * 8;
      #pragma unroll
      for (int nt = 0; nt < 8; nt++){
        int col = n0 + warpN * 64 + nt * 8 + (lane & 3) * 2;
        float2 v = make_float2(acc[mt][nt][ii*2] * SCALE, acc[mt][nt][ii*2+1] * SCALE);
        *(float2*)&out[(size_t)row * 1024 + col] = v;
      }
    }
  }
}

// ---------------- K4b: softmax rows of g_dots in-place ----------------
__global__ __launch_bounds__(256) void k_soft(){
  int row = blockIdx.x * 8 + (threadIdx.x >> 5);
  int lane = threadIdx.x & 31;
  float* r = g_dots + (size_t)row * 1024;
  float v[32];
  #pragma unroll
  for (int e = 0; e < 32; e++) v[e] = r[lane + e * 32];
  float m = v[0];
  #pragma unroll
  for (int e = 1; e < 32; e++) m = fmaxf(m, v[e]);
  m = allmax(m);
  float s = 0.f;
  #pragma unroll
  for (int e = 0; e < 32; e++){ v[e] = __expf(v[e] - m); s += v[e]; }
  s = allsum(s);
  float inv = 1.f / s;
  #pragma unroll
  for (int e = 0; e < 32; e++) r[lane + e * 32] = v[e] * inv;
}

// ---------------- K4c: agg GEMM (tf32) per (b,h): M=1024, N=288, K=1024 ------
__global__ __launch_bounds__(256) void k_agg(){
  __shared__ uint32_t As[16][132];
  __shared__ uint32_t Bs[16][100];
  int tid = threadIdx.x;
  int lane = tid & 31, warp = tid >> 5;
  int warpM = warp >> 1, warpN = warp & 1;
  int bh = blockIdx.z;
  int m0 = blockIdx.y * 128, n0 = blockIdx.x * 96;
  const float* Ap = g_dots + (size_t)bh * 1048576;
  const float* Bp = g_gf + (size_t)bh * 294912 + n0;

  float acc[2][6][4];
  #pragma unroll
  for (int mt = 0; mt < 2; mt++)
    #pragma unroll
    for (int nt = 0; nt < 6; nt++)
      #pragma unroll
      for (int i = 0; i < 4; i++) acc[mt][nt][i] = 0.f;

  int ar = tid >> 1, ac = (tid & 1) * 8;

  for (int k0 = 0; k0 < 1024; k0 += 16){
    float4 a0 = *(const float4*)(Ap + (size_t)(m0 + ar) * 1024 + k0 + ac);
    float4 a1 = *(const float4*)(Ap + (size_t)(m0 + ar) * 1024 + k0 + ac + 4);
    As[ac+0][ar]=f2tf32(a0.x); As[ac+1][ar]=f2tf32(a0.y);
    As[ac+2][ar]=f2tf32(a0.z); As[ac+3][ar]=f2tf32(a0.w);
    As[ac+4][ar]=f2tf32(a1.x); As[ac+5][ar]=f2tf32(a1.y);
    As[ac+6][ar]=f2tf32(a1.z); As[ac+7][ar]=f2tf32(a1.w);
    for (int l = tid; l < 1536; l += 256){
      int r = l / 96, c = l - r * 96;
      Bs[r][c] = f2tf32(Bp[(size_t)(k0 + r) * 288 + c]);
    }
    __syncthreads();
    #pragma unroll
    for (int kk = 0; kk < 16; kk += 8){
      uint32_t af[2][4], bf[6][2];
      int kr = kk + (lane & 3);
      #pragma unroll
      for (int mt = 0; mt < 2; mt++){
        int rb = warpM * 32 + mt * 16 + (lane >> 2);
        af[mt][0] = As[kr    ][rb];
        af[mt][1] = As[kr    ][rb + 8];
        af[mt][2] = As[kr + 4][rb];
        af[mt][3] = As[kr + 4][rb + 8];
      }
      #pragma unroll
      for (int nt = 0; nt < 6; nt++){
        int nb = warpN * 48 + nt * 8 + (lane >> 2);
        bf[nt][0] = Bs[kr    ][nb];
        bf[nt][1] = Bs[kr + 4][nb];
      }
      #pragma unroll
      for (int mt = 0; mt < 2; mt++)
        #pragma unroll
        for (int nt = 0; nt < 6; nt++)
          mma_tf32(acc[mt][nt], af[mt], bf[nt]);
    }
    __syncthreads();
  }
  float* out = g_agg + (size_t)bh * 294912;
  #pragma unroll
  for (int mt = 0; mt < 2; mt++){
    #pragma unroll
    for (int nt = 0; nt < 6; nt++){
      #pragma unroll
      for (int ii = 0; ii < 2; ii++){
        int row = m0 + warpM * 32 + mt * 16 + (lane >> 2) + ii * 8;
        int col = n0 + warpN * 48 + nt * 8 + (lane & 3) * 2;
        out[(size_t)row * 288 + col    ] = acc[mt][nt][ii * 2];
        out[(size_t)row * 288 + col + 1] = acc[mt][nt][ii * 2 + 1];
      }
    }
  }
}

// ---------------- K5: output projection (tf32) M=256, K=256, N=147456 -------------------
// block 128x128, grid (1152, 2); B gathered from g_agg
__global__ __launch_bounds__(256) void k_out(const float* __restrict__ W,
                                             const float* __restrict__ bias,
                                             float* __restrict__ out){
  __shared__ uint32_t As[16][132];
  __shared__ uint32_t Bs[16][132];
  int tid = threadIdx.x;
  int lane = tid & 31, warp = tid >> 5;
  int warpM = warp >> 1, warpN = warp & 1;
  int n0 = blockIdx.x * 128, m0 = blockIdx.y * 128;
  int b = n0 / PIX;
  int pix0 = n0 - b * PIX;

  // B gather precompute: thread owns column nb, k-half kh
  int nb = tid & 127;
  int kh = tid >> 7;                 // 0/1 -> 8 of the 16 k rows
  int pix = pix0 + nb;
  int y = pix / HWDIM, xc = pix - y * HWDIM;
  int g = (y / 3) * 32 + xc / 3;
  int win = (y % 3) * 3 + (xc % 3);
  size_t colbase = (size_t)b * 2359296 + (size_t)g * 288 + win * 32;

  int ar = tid >> 1, ac = (tid & 1) * 8;

  float acc[2][8][4];
  #pragma unroll
  for (int mt = 0; mt < 2; mt++)
    #pragma unroll
    for (int nt = 0; nt < 8; nt++)
      #pragma unroll
      for (int i = 0; i < 4; i++) acc[mt][nt][i] = 0.f;

  for (int k0 = 0; k0 < 256; k0 += 16){
    // A: W[256][256] row-major
    float4 a0 = *(const float4*)(W + (m0 + ar) * 256 + k0 + ac);
    float4 a1 = *(const float4*)(W + (m0 + ar) * 256 + k0 + ac + 4);
    As[ac+0][ar]=f2tf32(a0.x); As[ac+1][ar]=f2tf32(a0.y);
    As[ac+2][ar]=f2tf32(a0.z); As[ac+3][ar]=f2tf32(a0.w);
    As[ac+4][ar]=f2tf32(a1.x); As[ac+5][ar]=f2tf32(a1.y);
    As[ac+6][ar]=f2tf32(a1.z); As[ac+7][ar]=f2tf32(a1.w);
    // B gather: k = h*32 + d ; h = k0>>5, dbase = k0&31
    int h = k0 >> 5, dbase = (k0 & 31) + kh * 8;
    const float* bsrc = g_agg + colbase + (size_t)h * 294912 + dbase;
    float4 v0 = *(const float4*)(bsrc + 0);
    float4 v1 = *(const float4*)(bsrc + 4);
    int kb = kh * 8;
    Bs[kb+0][nb]=f2tf32(v0.x); Bs[kb+1][nb]=f2tf32(v0.y);
    Bs[kb+2][nb]=f2tf32(v0.z); Bs[kb+3][nb]=f2tf32(v0.w);
    Bs[kb+4][nb]=f2tf32(v1.x); Bs[kb+5][nb]=f2tf32(v1.y);
    Bs[kb+6][nb]=f2tf32(v1.z); Bs[kb+7][nb]=f2tf32(v1.w);
    __syncthreads();
    #pragma unroll
    for (int kk = 0; kk < 16; kk += 8){
      uint32_t af[2][4], bf[8][2];
      int kr = kk + (lane & 3);
      #pragma unroll
      for (int mt = 0; mt < 2; mt++){
        int rb = warpM * 32 + mt * 16 + (lane >> 2);
        af[mt][0] = As[kr    ][rb];
        af[mt][1] = As[kr    ][rb + 8];
        af[mt][2] = As[kr + 4][rb];
        af[mt][3] = As[kr + 4][rb + 8];
      }
      #pragma unroll
      for (int nt = 0; nt < 8; nt++){
        int nbc = warpN * 64 + nt * 8 + (lane >> 2);
        bf[nt][0] = Bs[kr    ][nbc];
        bf[nt][1] = Bs[kr + 4][nbc];
      }
      #pragma unroll
      for (int mt = 0; mt < 2; mt++)
        #pragma unroll
        for (int nt = 0; nt < 8; nt++)
          mma_tf32(acc[mt][nt], af[mt], bf[nt]);
    }
    __syncthreads();
  }
  // epilogue: +bias, store to out[(b*256+o)*PIX + pix]
  float* op = out + ((size_t)b * 256) * PIX + pix0;
  #pragma unroll
  for (int mt = 0; mt < 2; mt++){
    #pragma unroll
    for (int ii = 0; ii < 2; ii++){
      int o = m0 + warpM * 32 + mt * 16 + (lane >> 2) + ii * 8;
      float bi = bias[o];
      #pragma unroll
      for (int nt = 0; nt < 8; nt++){
        int col = warpN * 64 + nt * 8 + (lane & 3) * 2;
        float2 v = make_float2(acc[mt][nt][ii*2] + bi, acc[mt][nt][ii*2+1] + bi);
        *(float2*)&op[(size_t)o * PIX + col] = v;
      }
    }
  }
}

// ---------------- launch ----------------
extern "C" void kernel_launch(void* const* d_in, const int* in_sizes, int n_in,
                              void* d_out, int out_size){
  const float* x      = (const float*)d_in[0];
  const float* w_qkv  = (const float*)d_in[1];
  const float* gtok   = (const float*)d_in[2];
  const float* gamma  = (const float*)d_in[3];
  const float* beta   = (const float*)d_in[4];
  const float* w_qk   = (const float*)d_in[5];
  const float* b_qk   = (const float*)d_in[6];
  const float* w_out  = (const float*)d_in[7];
  const float* b_out  = (const float*)d_in[8];
  float* out = (float*)d_out;

  k_tok  <<<3, 256>>>(w_qkv, gtok);
  k_qkv  <<<dim3(1152, 6), 256>>>(w_qkv, x);
  k_attn1<<<16384, 256>>>(gamma, beta);
  k_qk   <<<dim3(8, 4, 16), 256>>>(w_qk, b_qk);
  k_dots <<<dim3(8, 8, 128), 256>>>();
  k_soft <<<16384, 256>>>();
  k_agg  <<<dim3(3, 8, 128), 256>>>();
  k_out  <<<dim3(1152, 2), 256>>>(w_out, b_out, out);
}

// round 5
// speedup vs baseline: 1.7717x; 1.0032x over previous
#include <cuda_runtime.h>
#include <cstdint>

// ---------------- problem constants ----------------
#define HWDIM 96
#define PIX   9216          // 96*96
#define NG    1024          // groups per image (32*32)
#define SCALE 0.17677669529663687f   // 32^-0.5

// ---------------- scratch (static device globals; no allocation) ----------------
__device__ float g_qkv[113246208];   // [gidx][768][9]
__device__ float g_tok[768];
__device__ float g_t[4194304];       // [b][256][1024]
__device__ float g_gf[37748736];     // [(b*8+h)*1024 + g][9][32]
__device__ float g_wq[4194304];      // [(b*8+h)*1024 + n][32]
__device__ float g_wkt[4194304];     // [(b*8+h)*32 + d][1024]
__device__ float g_dots[134217728];  // [(b*8+h)][1024][1024]
__device__ float g_agg[37748736];    // [(b*8+h)*1024 + i][9][32]

__device__ __forceinline__ float allsum(float v){
  #pragma unroll
  for (int o = 16; o > 0; o >>= 1) v += __shfl_xor_sync(0xffffffffu, v, o);
  return v;
}
__device__ __forceinline__ float allmax(float v){
  #pragma unroll
  for (int o = 16; o > 0; o >>= 1) v = fmaxf(v, __shfl_xor_sync(0xffffffffu, v, o));
  return v;
}
// FFMA-only exp (avoids MUFU.EX2 throughput wall: rt_SMSP=8 -> ~140G/s chip).
// Valid for x <= ~0 (post max-subtraction); clamped at -80 so the exponent-field
// add never wraps. Poly rel-err ~2e-6.
__device__ __forceinline__ float fexp(float x){
  x = fmaxf(x, -80.f);
  float t = fmaf(x, 1.4426950408889634f, 12582912.f);   // round(x*log2e) in low bits
  int e = __float_as_int(t) << 23;                      // (i)<<23  (magic low bits = 0)
  float i = t - 12582912.f;
  float f = fmaf(x, 1.4426950408889634f, -i);           // frac in [-0.5, 0.5]
  float p =       1.3333558e-3f;
  p = fmaf(p, f, 9.6181291e-3f);
  p = fmaf(p, f, 5.5504109e-2f);
  p = fmaf(p, f, 2.4022651e-1f);
  p = fmaf(p, f, 6.9314718e-1f);
  p = fmaf(p, f, 1.0f);
  return __int_as_float(__float_as_int(p) + e);
}
__device__ __forceinline__ uint32_t f2tf32(float v){
  uint32_t t;
  asm("cvt.rna.tf32.f32 %0, %1;" : "=r"(t) : "f"(v));
  return t;
}
__device__ __forceinline__ void mma_tf32(float* d, const uint32_t* a, const uint32_t* b){
  asm volatile(
    "mma.sync.aligned.m16n8k8.row.col.f32.tf32.tf32.f32 "
    "{%0,%1,%2,%3}, {%4,%5,%6,%7}, {%8,%9}, {%0,%1,%2,%3};\n"
    : "+f"(d[0]), "+f"(d[1]), "+f"(d[2]), "+f"(d[3])
    : "r"(a[0]), "r"(a[1]), "r"(a[2]), "r"(a[3]), "r"(b[0]), "r"(b[1]));
}

// ---------------- K0: qkv of the shared group token ----------------
__global__ void k_tok(const float* __restrict__ w, const float* __restrict__ tok){
  int o = blockIdx.x * 256 + threadIdx.x;
  if (o < 768){
    const float* wr = w + o * 256;
    float s = 0.f;
    #pragma unroll 8
    for (int c = 0; c < 256; c++) s += wr[c] * tok[c];
    g_tok[o] = s;
  }
}

// ---------------- K1: qkv GEMM (tf32)  M=768, K=256, N=147456 --------------
__global__ __launch_bounds__(256) void k_qkv(const float* __restrict__ A,
                                             const float* __restrict__ X){
  __shared__ uint32_t As[16][132];
  __shared__ uint32_t Bs[16][132];
  int tid = threadIdx.x;
  int lane = tid & 31, warp = tid >> 5;
  int warpM = warp >> 1, warpN = warp & 1;
  int m0 = blockIdx.y * 128;
  int n0 = blockIdx.x * 128;
  int b = n0 / PIX;
  int pix0 = n0 - b * PIX;
  const float* Bp = X + (size_t)b * 256 * PIX + pix0;

  float acc[2][8][4];
  #pragma unroll
  for (int mt = 0; mt < 2; mt++)
    #pragma unroll
    for (int nt = 0; nt < 8; nt++)
      #pragma unroll
      for (int i = 0; i < 4; i++) acc[mt][nt][i] = 0.f;

  int ar = tid >> 1, ac = (tid & 1) * 8;
  int br = tid >> 4, bc = (tid & 15) * 8;

  for (int k0 = 0; k0 < 256; k0 += 16){
    float4 a0 = *(const float4*)(A + (m0 + ar) * 256 + k0 + ac);
    float4 a1 = *(const float4*)(A + (m0 + ar) * 256 + k0 + ac + 4);
    As[ac+0][ar]=f2tf32(a0.x); As[ac+1][ar]=f2tf32(a0.y);
    As[ac+2][ar]=f2tf32(a0.z); As[ac+3][ar]=f2tf32(a0.w);
    As[ac+4][ar]=f2tf32(a1.x); As[ac+5][ar]=f2tf32(a1.y);
    As[ac+6][ar]=f2tf32(a1.z); As[ac+7][ar]=f2tf32(a1.w);
    float4 b0 = *(const float4*)(Bp + (size_t)(k0 + br) * PIX + bc);
    float4 b1 = *(const float4*)(Bp + (size_t)(k0 + br) * PIX + bc + 4);
    Bs[br][bc+0]=f2tf32(b0.x); Bs[br][bc+1]=f2tf32(b0.y);
    Bs[br][bc+2]=f2tf32(b0.z); Bs[br][bc+3]=f2tf32(b0.w);
    Bs[br][bc+4]=f2tf32(b1.x); Bs[br][bc+5]=f2tf32(b1.y);
    Bs[br][bc+6]=f2tf32(b1.z); Bs[br][bc+7]=f2tf32(b1.w);
    __syncthreads();
    #pragma unroll
    for (int kk = 0; kk < 16; kk += 8){
      uint32_t af[2][4], bf[8][2];
      int kr = kk + (lane & 3);
      #pragma unroll
      for (int mt = 0; mt < 2; mt++){
        int rb = warpM * 32 + mt * 16 + (lane >> 2);
        af[mt][0] = As[kr    ][rb];
        af[mt][1] = As[kr    ][rb + 8];
        af[mt][2] = As[kr + 4][rb];
        af[mt][3] = As[kr + 4][rb + 8];
      }
      #pragma unroll
      for (int nt = 0; nt < 8; nt++){
        int nb = warpN * 64 + nt * 8 + (lane >> 2);
        bf[nt][0] = Bs[kr    ][nb];
        bf[nt][1] = Bs[kr + 4][nb];
      }
      #pragma unroll
      for (int mt = 0; mt < 2; mt++)
        #pragma unroll
        for (int nt = 0; nt < 8; nt++)
          mma_tf32(acc[mt][nt], af[mt], bf[nt]);
    }
    __syncthreads();
  }
  #pragma unroll
  for (int nt = 0; nt < 8; nt++){
    #pragma unroll
    for (int jj = 0; jj < 2; jj++){
      int pix = pix0 + warpN * 64 + nt * 8 + (lane & 3) * 2 + jj;
      int y = pix / HWDIM, xc = pix - y * HWDIM;
      size_t base = ((size_t)(b * NG + (y / 3) * 32 + (xc / 3))) * 6912
                  + (y % 3) * 3 + (xc % 3);
      #pragma unroll
      for (int mt = 0; mt < 2; mt++){
        #pragma unroll
        for (int ii = 0; ii < 2; ii++){
          int o = m0 + warpM * 32 + mt * 16 + (lane >> 2) + ii * 8;
          g_qkv[base + (size_t)o * 9] = acc[mt][nt][ii * 2 + jj];
        }
      }
    }
  }
}

// ---------------- K2: per-group 10-token attention + LN + GELU ----------------
__global__ __launch_bounds__(256) void k_attn1(const float* __restrict__ gamma,
                                               const float* __restrict__ beta){
  __shared__ float sq[6912];
  __shared__ float stok[768];
  __shared__ float sd[8][10][10];
  int gidx = blockIdx.x;
  int b = gidx >> 10, g = gidx & 1023;
  int tid = threadIdx.x;

  const float4* src = (const float4*)(g_qkv + (size_t)gidx * 6912);
  for (int i = tid; i < 1728; i += 256) ((float4*)sq)[i] = src[i];
  for (int i = tid; i < 768; i += 256) stok[i] = g_tok[i];
  __syncthreads();

  int hh = tid >> 5, lane = tid & 31;
  int oq = hh * 32 + lane;

  float qr[10], kr[10], vr[10];
  qr[0] = stok[oq]; kr[0] = stok[oq + 256]; vr[0] = stok[oq + 512];
  #pragma unroll
  for (int n = 1; n < 10; n++){
    qr[n] = sq[oq * 9 + n - 1];
    kr[n] = sq[(oq + 256) * 9 + n - 1];
    vr[n] = sq[(oq + 512) * 9 + n - 1];
  }
  #pragma unroll
  for (int i = 0; i < 10; i++){
    #pragma unroll
    for (int j = 0; j < 10; j++){
      float t = allsum(qr[i] * kr[j]);
      if (lane == 0) sd[hh][i][j] = t * SCALE;
    }
  }
  __syncwarp();
  if (lane < 10){
    float row[10]; float m = -1e30f;
    #pragma unroll
    for (int j = 0; j < 10; j++){ row[j] = sd[hh][lane][j]; m = fmaxf(m, row[j]); }
    float s = 0.f;
    #pragma unroll
    for (int j = 0; j < 10; j++){ row[j] = fexp(row[j] - m); s += row[j]; }
    float inv = 1.f / s;
    #pragma unroll
    for (int j = 0; j < 10; j++) sd[hh][lane][j] = row[j] * inv;
  }
  __syncwarp();
  float x0 = 0.f;
  #pragma unroll
  for (int j = 0; j < 10; j++) x0 = fmaf(sd[hh][0][j], vr[j], x0);
  float mu = allsum(x0) * 0.03125f;
  float dv = x0 - mu;
  float var = allsum(dv * dv) * 0.03125f;
  float xn = dv * rsqrtf(var + 1e-5f) * gamma[lane] + beta[lane];
  float ge = 0.5f * xn * (1.f + erff(xn * 0.70710678118654752f));
  g_t[b * 262144 + oq * 1024 + g] = ge;

  size_t gfb = ((size_t)(b * 8 + hh) * NG + g) * 288 + lane;
  #pragma unroll
  for (int i = 1; i < 10; i++){
    float o = 0.f;
    #pragma unroll
    for (int j = 0; j < 10; j++) o = fmaf(sd[hh][i][j], vr[j], o);
    g_gf[gfb + (i - 1) * 32] = o;
  }
}

// ---------------- K3: qk GEMM (tf32) per-batch M=512, K=256, N=1024 ----------------
__global__ __launch_bounds__(256) void k_qk(const float* __restrict__ A,
                                            const float* __restrict__ bias){
  __shared__ uint32_t As[16][132];
  __shared__ uint32_t Bs[16][132];
  int tid = threadIdx.x;
  int lane = tid & 31, warp = tid >> 5;
  int warpM = warp >> 1, warpN = warp & 1;
  int n0 = blockIdx.x * 128, m0 = blockIdx.y * 128, b = blockIdx.z;
  const float* Bp = g_t + b * 262144;

  float acc[2][8][4];
  #pragma unroll
  for (int mt = 0; mt < 2; mt++)
    #pragma unroll
    for (int nt = 0; nt < 8; nt++)
      #pragma unroll
      for (int i = 0; i < 4; i++) acc[mt][nt][i] = 0.f;

  int ar = tid >> 1, ac = (tid & 1) * 8;
  int br = tid >> 4, bc = (tid & 15) * 8;

  for (int k0 = 0; k0 < 256; k0 += 16){
    float4 a0 = *(const float4*)(A + (m0 + ar) * 256 + k0 + ac);
    float4 a1 = *(const float4*)(A + (m0 + ar) * 256 + k0 + ac + 4);
    As[ac+0][ar]=f2tf32(a0.x); As[ac+1][ar]=f2tf32(a0.y);
    As[ac+2][ar]=f2tf32(a0.z); As[ac+3][ar]=f2tf32(a0.w);
    As[ac+4][ar]=f2tf32(a1.x); As[ac+5][ar]=f2tf32(a1.y);
    As[ac+6][ar]=f2tf32(a1.z); As[ac+7][ar]=f2tf32(a1.w);
    float4 b0 = *(const float4*)(Bp + (k0 + br) * 1024 + n0 + bc);
    float4 b1 = *(const float4*)(Bp + (k0 + br) * 1024 + n0 + bc + 4);
    Bs[br][bc+0]=f2tf32(b0.x); Bs[br][bc+1]=f2tf32(b0.y);
    Bs[br][bc+2]=f2tf32(b0.z); Bs[br][bc+3]=f2tf32(b0.w);
    Bs[br][bc+4]=f2tf32(b1.x); Bs[br][bc+5]=f2tf32(b1.y);
    Bs[br][bc+6]=f2tf32(b1.z); Bs[br][bc+7]=f2tf32(b1.w);
    __syncthreads();
    #pragma unroll
    for (int kk = 0; kk < 16; kk += 8){
      uint32_t af[2][4], bf[8][2];
      int kr = kk + (lane & 3);
      #pragma unroll
      for (int mt = 0; mt < 2; mt++){
        int rb = warpM * 32 + mt * 16 + (lane >> 2);
        af[mt][0] = As[kr    ][rb];
        af[mt][1] = As[kr    ][rb + 8];
        af[mt][2] = As[kr + 4][rb];
        af[mt][3] = As[kr + 4][rb + 8];
      }
      #pragma unroll
      for (int nt = 0; nt < 8; nt++){
        int nb = warpN * 64 + nt * 8 + (lane >> 2);
        bf[nt][0] = Bs[kr    ][nb];
        bf[nt][1] = Bs[kr + 4][nb];
      }
      #pragma unroll
      for (int mt = 0; mt < 2; mt++)
        #pragma unroll
        for (int nt = 0; nt < 8; nt++)
          mma_tf32(acc[mt][nt], af[mt], bf[nt]);
    }
    __syncthreads();
  }
  #pragma unroll
  for (int mt = 0; mt < 2; mt++){
    #pragma unroll
    for (int ii = 0; ii < 2; ii++){
      int o = m0 + warpM * 32 + mt * 16 + (lane >> 2) + ii * 8;
      float bi = bias[o];
      int h = o >> 6, dd = o & 63;
      #pragma unroll
      for (int nt = 0; nt < 8; nt++){
        #pragma unroll
        for (int jj = 0; jj < 2; jj++){
          int n = n0 + warpN * 64 + nt * 8 + (lane & 3) * 2 + jj;
          float v = acc[mt][nt][ii * 2 + jj] + bi;
          if (dd < 32) g_wq[((b * 8 + h) * 1024 + n) * 32 + dd] = v;
          else         g_wkt[((b * 8 + h) * 32 + (dd - 32)) * 1024 + n] = v;
        }
      }
    }
  }
}

// ---------------- K4a: window dots (tf32) per (b,h): M=1024, N=1024, K=32 ---------------
__global__ __launch_bounds__(256) void k_dots(){
  __shared__ uint32_t As[32][132];
  __shared__ uint32_t Bs[32][132];
  int tid = threadIdx.x;
  int lane = tid & 31, warp = tid >> 5;
  int warpM = warp >> 1, warpN = warp & 1;
  int bh = blockIdx.z;
  int m0 = blockIdx.y * 128, n0 = blockIdx.x * 128;
  const float* Ap = g_wq + bh * 32768;    // [1024][32]
  const float* Bp = g_wkt + bh * 32768;   // [32][1024]

  int ar = tid >> 1, ac = (tid & 1) * 16;
  #pragma unroll
  for (int i = 0; i < 16; i += 4){
    float4 v = *(const float4*)(Ap + (m0 + ar) * 32 + ac + i);
    As[ac+i+0][ar]=f2tf32(v.x); As[ac+i+1][ar]=f2tf32(v.y);
    As[ac+i+2][ar]=f2tf32(v.z); As[ac+i+3][ar]=f2tf32(v.w);
  }
  int br = tid >> 3, bc = (tid & 7) * 16;
  #pragma unroll
  for (int i = 0; i < 16; i += 4){
    float4 v = *(const float4*)(Bp + br * 1024 + n0 + bc + i);
    Bs[br][bc+i+0]=f2tf32(v.x); Bs[br][bc+i+1]=f2tf32(v.y);
    Bs[br][bc+i+2]=f2tf32(v.z); Bs[br][bc+i+3]=f2tf32(v.w);
  }
  __syncthreads();

  float acc[2][8][4];
  #pragma unroll
  for (int mt = 0; mt < 2; mt++)
    #pragma unroll
    for (int nt = 0; nt < 8; nt++)
      #pragma unroll
      for (int i = 0; i < 4; i++) acc[mt][nt][i] = 0.f;

  #pragma unroll
  for (int kk = 0; kk < 32; kk += 8){
    uint32_t af[2][4], bf[8][2];
    int kr = kk + (lane & 3);
    #pragma unroll
    for (int mt = 0; mt < 2; mt++){
      int rb = warpM * 32 + mt * 16 + (lane >> 2);
      af[mt][0] = As[kr    ][rb];
      af[mt][1] = As[kr    ][rb + 8];
      af[mt][2] = As[kr + 4][rb];
      af[mt][3] = As[kr + 4][rb + 8];
    }
    #pragma unroll
    for (int nt = 0; nt < 8; nt++){
      int nb = warpN * 64 + nt * 8 + (lane >> 2);
      bf[nt][0] = Bs[kr    ][nb];
      bf[nt][1] = Bs[kr + 4][nb];
    }
    #pragma unroll
    for (int mt = 0; mt < 2; mt++)
      #pragma unroll
      for (int nt = 0; nt < 8; nt++)
        mma_tf32(acc[mt][nt], af[mt], bf[nt]);
  }
  float* out = g_dots + (size_t)bh * 1048576;
  #pragma unroll
  for (int mt = 0; mt < 2; mt++){
    #pragma unroll
    for (int ii = 0; ii < 2; ii++){
      int row = m0 + warpM * 32 + mt * 16 + (lane >> 2) + ii * 8;
      #pragma unroll
      for (int nt = 0; nt < 8; nt++){
        int col = n0 + warpN * 64 + nt * 8 + (lane & 3) * 2;
        float2 v = make_float2(acc[mt][nt][ii*2] * SCALE, acc[mt][nt][ii*2+1] * SCALE);
        *(float2*)&out[(size_t)row * 1024 + col] = v;
      }
    }
  }
}

// ---------------- K4b: softmax rows of g_dots in-place (FFMA exp, float4 I/O) -----------
__global__ __launch_bounds__(256) void k_soft(){
  int row = blockIdx.x * 8 + (threadIdx.x >> 5);
  int lane = threadIdx.x & 31;
  float4* r = (float4*)(g_dots + (size_t)row * 1024);
  float4 v[8];
  #pragma unroll
  for (int e = 0; e < 8; e++) v[e] = r[lane + e * 32];
  float m = -1e30f;
  #pragma unroll
  for (int e = 0; e < 8; e++){
    m = fmaxf(m, fmaxf(fmaxf(v[e].x, v[e].y), fmaxf(v[e].z, v[e].w)));
  }
  m = allmax(m);
  float s = 0.f;
  #pragma unroll
  for (int e = 0; e < 8; e++){
    v[e].x = fexp(v[e].x - m); v[e].y = fexp(v[e].y - m);
    v[e].z = fexp(v[e].z - m); v[e].w = fexp(v[e].w - m);
    s += (v[e].x + v[e].y) + (v[e].z + v[e].w);
  }
  s = allsum(s);
  float inv = 1.f / s;
  #pragma unroll
  for (int e = 0; e < 8; e++){
    v[e].x *= inv; v[e].y *= inv; v[e].z *= inv; v[e].w *= inv;
    r[lane + e * 32] = v[e];
  }
}

// ---------------- K4c: agg GEMM (tf32) per (b,h): M=1024, N=288, K=1024 ------
__global__ __launch_bounds__(256) void k_agg(){
  __shared__ uint32_t As[16][132];
  __shared__ uint32_t Bs[16][100];
  int tid = threadIdx.x;
  int lane = tid & 31, warp = tid >> 5;
  int warpM = warp >> 1, warpN = warp & 1;
  int bh = blockIdx.z;
  int m0 = blockIdx.y * 128, n0 = blockIdx.x * 96;
  const float* Ap = g_dots + (size_t)bh * 1048576;
  const float* Bp = g_gf + (size_t)bh * 294912 + n0;

  float acc[2][6][4];
  #pragma unroll
  for (int mt = 0; mt < 2; mt++)
    #pragma unroll
    for (int nt = 0; nt < 6; nt++)
      #pragma unroll
      for (int i = 0; i < 4; i++) acc[mt][nt][i] = 0.f;

  int ar = tid >> 1, ac = (tid & 1) * 8;

  for (int k0 = 0; k0 < 1024; k0 += 16){
    float4 a0 = *(const float4*)(Ap + (size_t)(m0 + ar) * 1024 + k0 + ac);
    float4 a1 = *(const float4*)(Ap + (size_t)(m0 + ar) * 1024 + k0 + ac + 4);
    As[ac+0][ar]=f2tf32(a0.x); As[ac+1][ar]=f2tf32(a0.y);
    As[ac+2][ar]=f2tf32(a0.z); As[ac+3][ar]=f2tf32(a0.w);
    As[ac+4][ar]=f2tf32(a1.x); As[ac+5][ar]=f2tf32(a1.y);
    As[ac+6][ar]=f2tf32(a1.z); As[ac+7][ar]=f2tf32(a1.w);
    for (int l = tid; l < 1536; l += 256){
      int r = l / 96, c = l - r * 96;
      Bs[r][c] = f2tf32(Bp[(size_t)(k0 + r) * 288 + c]);
    }
    __syncthreads();
    #pragma unroll
    for (int kk = 0; kk < 16; kk += 8){
      uint32_t af[2][4], bf[6][2];
      int kr = kk + (lane & 3);
      #pragma unroll
      for (int mt = 0; mt < 2; mt++){
        int rb = warpM * 32 + mt * 16 + (lane >> 2);
        af[mt][0] = As[kr    ][rb];
        af[mt][1] = As[kr    ][rb + 8];
        af[mt][2] = As[kr + 4][rb];
        af[mt][3] = As[kr + 4][rb + 8];
      }
      #pragma unroll
      for (int nt = 0; nt < 6; nt++){
        int nb = warpN * 48 + nt * 8 + (lane >> 2);
        bf[nt][0] = Bs[kr    ][nb];
        bf[nt][1] = Bs[kr + 4][nb];
      }
      #pragma unroll
      for (int mt = 0; mt < 2; mt++)
        #pragma unroll
        for (int nt = 0; nt < 6; nt++)
          mma_tf32(acc[mt][nt], af[mt], bf[nt]);
    }
    __syncthreads();
  }
  float* out = g_agg + (size_t)bh * 294912;
  #pragma unroll
  for (int mt = 0; mt < 2; mt++){
    #pragma unroll
    for (int nt = 0; nt < 6; nt++){
      #pragma unroll
      for (int ii = 0; ii < 2; ii++){
        int row = m0 + warpM * 32 + mt * 16 + (lane >> 2) + ii * 8;
        int col = n0 + warpN * 48 + nt * 8 + (lane & 3) * 2;
        out[(size_t)row * 288 + col    ] = acc[mt][nt][ii * 2];
        out[(size_t)row * 288 + col + 1] = acc[mt][nt][ii * 2 + 1];
      }
    }
  }
}

// ---------------- K5: output projection (tf32) M=256, K=256, N=147456 -------------------
__global__ __launch_bounds__(256) void k_out(const float* __restrict__ W,
                                             const float* __restrict__ bias,
                                             float* __restrict__ out){
  __shared__ uint32_t As[16][132];
  __shared__ uint32_t Bs[16][132];
  int tid = threadIdx.x;
  int lane = tid & 31, warp = tid >> 5;
  int warpM = warp >> 1, warpN = warp & 1;
  int n0 = blockIdx.x * 128, m0 = blockIdx.y * 128;
  int b = n0 / PIX;
  int pix0 = n0 - b * PIX;

  int nb = tid & 127;
  int kh = tid >> 7;
  int pix = pix0 + nb;
  int y = pix / HWDIM, xc = pix - y * HWDIM;
  int g = (y / 3) * 32 + xc / 3;
  int win = (y % 3) * 3 + (xc % 3);
  size_t colbase = (size_t)b * 2359296 + (size_t)g * 288 + win * 32;

  int ar = tid >> 1, ac = (tid & 1) * 8;

  float acc[2][8][4];
  #pragma unroll
  for (int mt = 0; mt < 2; mt++)
    #pragma unroll
    for (int nt = 0; nt < 8; nt++)
      #pragma unroll
      for (int i = 0; i < 4; i++) acc[mt][nt][i] = 0.f;

  for (int k0 = 0; k0 < 256; k0 += 16){
    float4 a0 = *(const float4*)(W + (m0 + ar) * 256 + k0 + ac);
    float4 a1 = *(const float4*)(W + (m0 + ar) * 256 + k0 + ac + 4);
    As[ac+0][ar]=f2tf32(a0.x); As[ac+1][ar]=f2tf32(a0.y);
    As[ac+2][ar]=f2tf32(a0.z); As[ac+3][ar]=f2tf32(a0.w);
    As[ac+4][ar]=f2tf32(a1.x); As[ac+5][ar]=f2tf32(a1.y);
    As[ac+6][ar]=f2tf32(a1.z); As[ac+7][ar]=f2tf32(a1.w);
    int h = k0 >> 5, dbase = (k0 & 31) + kh * 8;
    const float* bsrc = g_agg + colbase + (size_t)h * 294912 + dbase;
    float4 v0 = *(const float4*)(bsrc + 0);
    float4 v1 = *(const float4*)(bsrc + 4);
    int kb = kh * 8;
    Bs[kb+0][nb]=f2tf32(v0.x); Bs[kb+1][nb]=f2tf32(v0.y);
    Bs[kb+2][nb]=f2tf32(v0.z); Bs[kb+3][nb]=f2tf32(v0.w);
    Bs[kb+4][nb]=f2tf32(v1.x); Bs[kb+5][nb]=f2tf32(v1.y);
    Bs[kb+6][nb]=f2tf32(v1.z); Bs[kb+7][nb]=f2tf32(v1.w);
    __syncthreads();
    #pragma unroll
    for (int kk = 0; kk < 16; kk += 8){
      uint32_t af[2][4], bf[8][2];
      int kr = kk + (lane & 3);
      #pragma unroll
      for (int mt = 0; mt < 2; mt++){
        int rb = warpM * 32 + mt * 16 + (lane >> 2);
        af[mt][0] = As[kr    ][rb];
        af[mt][1] = As[kr    ][rb + 8];
        af[mt][2] = As[kr + 4][rb];
        af[mt][3] = As[kr + 4][rb + 8];
      }
      #pragma unroll
      for (int nt = 0; nt < 8; nt++){
        int nbc = warpN * 64 + nt * 8 + (lane >> 2);
        bf[nt][0] = Bs[kr    ][nbc];
        bf[nt][1] = Bs[kr + 4][nbc];
      }
      #pragma unroll
      for (int mt = 0; mt < 2; mt++)
        #pragma unroll
        for (int nt = 0; nt < 8; nt++)
          mma_tf32(acc[mt][nt], af[mt], bf[nt]);
    }
    __syncthreads();
  }
  float* op = out + ((size_t)b * 256) * PIX + pix0;
  #pragma unroll
  for (int mt = 0; mt < 2; mt++){
    #pragma unroll
    for (int ii = 0; ii < 2; ii++){
      int o = m0 + warpM * 32 + mt * 16 + (lane >> 2) + ii * 8;
      float bi = bias[o];
      #pragma unroll
      for (int nt = 0; nt < 8; nt++){
        int col = warpN * 64 + nt * 8 + (lane & 3) * 2;
        float2 v = make_float2(acc[mt][nt][ii*2] + bi, acc[mt][nt][ii*2+1] + bi);
        *(float2*)&op[(size_t)o * PIX + col] = v;
      }
    }
  }
}

// ---------------- launch ----------------
extern "C" void kernel_launch(void* const* d_in, const int* in_sizes, int n_in,
                              void* d_out, int out_size){
  const float* x      = (const float*)d_in[0];
  const float* w_qkv  = (const float*)d_in[1];
  const float* gtok   = (const float*)d_in[2];
  const float* gamma  = (const float*)d_in[3];
  const float* beta   = (const float*)d_in[4];
  const float* w_qk   = (const float*)d_in[5];
  const float* b_qk   = (const float*)d_in[6];
  const float* w_out  = (const float*)d_in[7];
  const float* b_out  = (const float*)d_in[8];
  float* out = (float*)d_out;

  k_tok  <<<3, 256>>>(w_qkv, gtok);
  k_qkv  <<<dim3(1152, 6), 256>>>(w_qkv, x);
  k_attn1<<<16384, 256>>>(gamma, beta);
  k_qk   <<<dim3(8, 4, 16), 256>>>(w_qk, b_qk);
  k_dots <<<dim3(8, 8, 128), 256>>>();
  k_soft <<<16384, 256>>>();
  k_agg  <<<dim3(3, 8, 128), 256>>>();
  k_out  <<<dim3(1152, 2), 256>>>(w_out, b_out, out);
}

// round 7
// speedup vs baseline: 1.8783x; 1.0602x over previous
#include <cuda_runtime.h>
#include <cstdint>

// ---------------- problem constants ----------------
#define HWDIM 96
#define PIX   9216          // 96*96
#define NG    1024          // groups per image (32*32)
#define SCALE 0.17677669529663687f   // 32^-0.5

// ---------------- scratch (static device globals; no allocation) ----------------
__device__ float g_qkv[113246208];   // [b][768][9216]  (plain GEMM layout, coalesced)
__device__ float g_tok[768];
__device__ float g_t[4194304];       // [b][256][1024]
__device__ float g_gf[37748736];     // [(b*8+h)*1024 + g][9][32]
__device__ float g_wq[4194304];      // [(b*8+h)*1024 + n][32]
__device__ float g_wkt[4194304];     // [(b*8+h)*32 + d][1024]
__device__ float g_dots[134217728];  // [(b*8+h)][1024][1024]  raw scaled logits
__device__ unsigned g_rmax[131072];  // per-row encoded max  [(b*8+h)*1024 + i]
__device__ float g_agg[37748736];    // [(b*8+h)*1024 + i][9][32]

__device__ __forceinline__ float allsum(float v){
  #pragma unroll
  for (int o = 16; o > 0; o >>= 1) v += __shfl_xor_sync(0xffffffffu, v, o);
  return v;
}
// float -> order-preserving uint encoding (for atomicMax); 0 is a -inf sentinel.
__device__ __forceinline__ unsigned fenc(float f){
  unsigned u = __float_as_uint(f);
  return (u & 0x80000000u) ? ~u : (u | 0x80000000u);
}
__device__ __forceinline__ float fdec(unsigned u){
  return (u & 0x80000000u) ? __uint_as_float(u ^ 0x80000000u) : __uint_as_float(~u);
}
// FFMA-only exp; valid for x <= 0 (post max-subtraction), clamped at -80.
__device__ __forceinline__ float fexp(float x){
  x = fmaxf(x, -80.f);
  float t = fmaf(x, 1.4426950408889634f, 12582912.f);
  int e = __float_as_int(t) << 23;
  float i = t - 12582912.f;
  float f = fmaf(x, 1.4426950408889634f, -i);
  float p =       1.3333558e-3f;
  p = fmaf(p, f, 9.6181291e-3f);
  p = fmaf(p, f, 5.5504109e-2f);
  p = fmaf(p, f, 2.4022651e-1f);
  p = fmaf(p, f, 6.9314718e-1f);
  p = fmaf(p, f, 1.0f);
  return __int_as_float(__float_as_int(p) + e);
}
__device__ __forceinline__ uint32_t f2tf32(float v){
  uint32_t t;
  asm("cvt.rna.tf32.f32 %0, %1;" : "=r"(t) : "f"(v));
  return t;
}
__device__ __forceinline__ void mma_tf32(float* d, const uint32_t* a, const uint32_t* b){
  asm volatile(
    "mma.sync.aligned.m16n8k8.row.col.f32.tf32.tf32.f32 "
    "{%0,%1,%2,%3}, {%4,%5,%6,%7}, {%8,%9}, {%0,%1,%2,%3};\n"
    : "+f"(d[0]), "+f"(d[1]), "+f"(d[2]), "+f"(d[3])
    : "r"(a[0]), "r"(a[1]), "r"(a[2]), "r"(a[3]), "r"(b[0]), "r"(b[1]));
}

// ---------------- K-1: zero the rowmax array (sentinel = 0 == -inf) ----------------
__global__ void k_zero(){
  ((uint4*)g_rmax)[blockIdx.x * 256 + threadIdx.x] = make_uint4(0,0,0,0);
}

// ---------------- K0: qkv of the shared group token ----------------
__global__ void k_tok(const float* __restrict__ w, const float* __restrict__ tok){
  int o = blockIdx.x * 256 + threadIdx.x;
  if (o < 768){
    const float* wr = w + o * 256;
    float s = 0.f;
    #pragma unroll 8
    for (int c = 0; c < 256; c++) s += wr[c] * tok[c];
    g_tok[o] = s;
  }
}

// ---------------- K1: qkv GEMM (tf32)  M=768, K=256, N=147456 ; coalesced output --------
__global__ __launch_bounds__(256) void k_qkv(const float* __restrict__ A,
                                             const float* __restrict__ X){
  __shared__ uint32_t As[16][132];
  __shared__ uint32_t Bs[16][132];
  int tid = threadIdx.x;
  int lane = tid & 31, warp = tid >> 5;
  int warpM = warp >> 1, warpN = warp & 1;
  int m0 = blockIdx.y * 128;
  int n0 = blockIdx.x * 128;
  int b = n0 / PIX;
  int pix0 = n0 - b * PIX;
  const float* Bp = X + (size_t)b * 256 * PIX + pix0;

  float acc[2][8][4];
  #pragma unroll
  for (int mt = 0; mt < 2; mt++)
    #pragma unroll
    for (int nt = 0; nt < 8; nt++)
      #pragma unroll
      for (int i = 0; i < 4; i++) acc[mt][nt][i] = 0.f;

  int ar = tid >> 1, ac = (tid & 1) * 8;
  int br = tid >> 4, bc = (tid & 15) * 8;

  for (int k0 = 0; k0 < 256; k0 += 16){
    float4 a0 = *(const float4*)(A + (m0 + ar) * 256 + k0 + ac);
    float4 a1 = *(const float4*)(A + (m0 + ar) * 256 + k0 + ac + 4);
    As[ac+0][ar]=f2tf32(a0.x); As[ac+1][ar]=f2tf32(a0.y);
    As[ac+2][ar]=f2tf32(a0.z); As[ac+3][ar]=f2tf32(a0.w);
    As[ac+4][ar]=f2tf32(a1.x); As[ac+5][ar]=f2tf32(a1.y);
    As[ac+6][ar]=f2tf32(a1.z); As[ac+7][ar]=f2tf32(a1.w);
    float4 b0 = *(const float4*)(Bp + (size_t)(k0 + br) * PIX + bc);
    float4 b1 = *(const float4*)(Bp + (size_t)(k0 + br) * PIX + bc + 4);
    Bs[br][bc+0]=f2tf32(b0.x); Bs[br][bc+1]=f2tf32(b0.y);
    Bs[br][bc+2]=f2tf32(b0.z); Bs[br][bc+3]=f2tf32(b0.w);
    Bs[br][bc+4]=f2tf32(b1.x); Bs[br][bc+5]=f2tf32(b1.y);
    Bs[br][bc+6]=f2tf32(b1.z); Bs[br][bc+7]=f2tf32(b1.w);
    __syncthreads();
    #pragma unroll
    for (int kk = 0; kk < 16; kk += 8){
      uint32_t af[2][4], bf[8][2];
      int kr = kk + (lane & 3);
      #pragma unroll
      for (int mt = 0; mt < 2; mt++){
        int rb = warpM * 32 + mt * 16 + (lane >> 2);
        af[mt][0] = As[kr    ][rb];
        af[mt][1] = As[kr    ][rb + 8];
        af[mt][2] = As[kr + 4][rb];
        af[mt][3] = As[kr + 4][rb + 8];
      }
      #pragma unroll
      for (int nt = 0; nt < 8; nt++){
        int nb = warpN * 64 + nt * 8 + (lane >> 2);
        bf[nt][0] = Bs[kr    ][nb];
        bf[nt][1] = Bs[kr + 4][nb];
      }
      #pragma unroll
      for (int mt = 0; mt < 2; mt++)
        #pragma unroll
        for (int nt = 0; nt < 8; nt++)
          mma_tf32(acc[mt][nt], af[mt], bf[nt]);
    }
    __syncthreads();
  }
  // coalesced epilogue: g_qkv[(b*768+o)*PIX + pix]
  float* outp = g_qkv + (size_t)b * 768 * PIX + pix0;
  #pragma unroll
  for (int mt = 0; mt < 2; mt++){
    #pragma unroll
    for (int ii = 0; ii < 2; ii++){
      int o = m0 + warpM * 32 + mt * 16 + (lane >> 2) + ii * 8;
      #pragma unroll
      for (int nt = 0; nt < 8; nt++){
        int col = warpN * 64 + nt * 8 + (lane & 3) * 2;
        float2 v = make_float2(acc[mt][nt][ii*2], acc[mt][nt][ii*2+1]);
        *(float2*)&outp[(size_t)o * PIX + col] = v;
      }
    }
  }
}

// ---------------- K2: per-group 10-token attention + LN + GELU ----------------
__global__ __launch_bounds__(256) void k_attn1(const float* __restrict__ gamma,
                                               const float* __restrict__ beta){
  __shared__ float sq[6912];        // [o][win]
  __shared__ float stok[768];
  __shared__ float sd[8][10][10];
  int gidx = blockIdx.x;
  int b = gidx >> 10, g = gidx & 1023;
  int gy = g >> 5, gx = g & 31;
  int tid = threadIdx.x;

  // gather the 9 group pixels from plain layout
  const float* src = g_qkv + (size_t)b * 768 * PIX + (gy * 3) * HWDIM + gx * 3;
  for (int i = tid; i < 6912; i += 256){
    int o = i / 9, win = i - o * 9;
    int r = win / 3, c = win - r * 3;
    sq[i] = src[(size_t)o * PIX + r * HWDIM + c];
  }
  for (int i = tid; i < 768; i += 256) stok[i] = g_tok[i];
  __syncthreads();

  int hh = tid >> 5, lane = tid & 31;
  int oq = hh * 32 + lane;

  float qr[10], kr[10], vr[10];
  qr[0] = stok[oq]; kr[0] = stok[oq + 256]; vr[0] = stok[oq + 512];
  #pragma unroll
  for (int n = 1; n < 10; n++){
    qr[n] = sq[oq * 9 + n - 1];
    kr[n] = sq[(oq + 256) * 9 + n - 1];
    vr[n] = sq[(oq + 512) * 9 + n - 1];
  }
  #pragma unroll
  for (int i = 0; i < 10; i++){
    #pragma unroll
    for (int j = 0; j < 10; j++){
      float t = allsum(qr[i] * kr[j]);
      if (lane == 0) sd[hh][i][j] = t * SCALE;
    }
  }
  __syncwarp();
  if (lane < 10){
    float row[10]; float m = -1e30f;
    #pragma unroll
    for (int j = 0; j < 10; j++){ row[j] = sd[hh][lane][j]; m = fmaxf(m, row[j]); }
    float s = 0.f;
    #pragma unroll
    for (int j = 0; j < 10; j++){ row[j] = fexp(row[j] - m); s += row[j]; }
    float inv = 1.f / s;
    #pragma unroll
    for (int j = 0; j < 10; j++) sd[hh][lane][j] = row[j] * inv;
  }
  __syncwarp();
  float x0 = 0.f;
  #pragma unroll
  for (int j = 0; j < 10; j++) x0 = fmaf(sd[hh][0][j], vr[j], x0);
  float mu = allsum(x0) * 0.03125f;
  float dv = x0 - mu;
  float var = allsum(dv * dv) * 0.03125f;
  float xn = dv * rsqrtf(var + 1e-5f) * gamma[lane] + beta[lane];
  float ge = 0.5f * xn * (1.f + erff(xn * 0.70710678118654752f));
  g_t[b * 262144 + oq * 1024 + g] = ge;

  size_t gfb = ((size_t)(b * 8 + hh) * NG + g) * 288 + lane;
  #pragma unroll
  for (int i = 1; i < 10; i++){
    float o = 0.f;
    #pragma unroll
    for (int j = 0; j < 10; j++) o = fmaf(sd[hh][i][j], vr[j], o);
    g_gf[gfb + (i - 1) * 32] = o;
  }
}

// ---------------- K3: qk GEMM (tf32) per-batch M=512, K=256, N=1024 ----------------
__global__ __launch_bounds__(256) void k_qk(const float* __restrict__ A,
                                            const float* __restrict__ bias){
  __shared__ uint32_t As[16][132];
  __shared__ uint32_t Bs[16][132];
  int tid = threadIdx.x;
  int lane = tid & 31, warp = tid >> 5;
  int warpM = warp >> 1, warpN = warp & 1;
  int n0 = blockIdx.x * 128, m0 = blockIdx.y * 128, b = blockIdx.z;
  const float* Bp = g_t + b * 262144;

  float acc[2][8][4];
  #pragma unroll
  for (int mt = 0; mt < 2; mt++)
    #pragma unroll
    for (int nt = 0; nt < 8; nt++)
      #pragma unroll
      for (int i = 0; i < 4; i++) acc[mt][nt][i] = 0.f;

  int ar = tid >> 1, ac = (tid & 1) * 8;
  int br = tid >> 4, bc = (tid & 15) * 8;

  for (int k0 = 0; k0 < 256; k0 += 16){
    float4 a0 = *(const float4*)(A + (m0 + ar) * 256 + k0 + ac);
    float4 a1 = *(const float4*)(A + (m0 + ar) * 256 + k0 + ac + 4);
    As[ac+0][ar]=f2tf32(a0.x); As[ac+1][ar]=f2tf32(a0.y);
    As[ac+2][ar]=f2tf32(a0.z); As[ac+3][ar]=f2tf32(a0.w);
    As[ac+4][ar]=f2tf32(a1.x); As[ac+5][ar]=f2tf32(a1.y);
    As[ac+6][ar]=f2tf32(a1.z); As[ac+7][ar]=f2tf32(a1.w);
    float4 b0 = *(const float4*)(Bp + (k0 + br) * 1024 + n0 + bc);
    float4 b1 = *(const float4*)(Bp + (k0 + br) * 1024 + n0 + bc + 4);
    Bs[br][bc+0]=f2tf32(b0.x); Bs[br][bc+1]=f2tf32(b0.y);
    Bs[br][bc+2]=f2tf32(b0.z); Bs[br][bc+3]=f2tf32(b0.w);
    Bs[br][bc+4]=f2tf32(b1.x); Bs[br][bc+5]=f2tf32(b1.y);
    Bs[br][bc+6]=f2tf32(b1.z); Bs[br][bc+7]=f2tf32(b1.w);
    __syncthreads();
    #pragma unroll
    for (int kk = 0; kk < 16; kk += 8){
      uint32_t af[2][4], bf[8][2];
      int kr = kk + (lane & 3);
      #pragma unroll
      for (int mt = 0; mt < 2; mt++){
        int rb = warpM * 32 + mt * 16 + (lane >> 2);
        af[mt][0] = As[kr    ][rb];
        af[mt][1] = As[kr    ][rb + 8];
        af[mt][2] = As[kr + 4][rb];
        af[mt][3] = As[kr + 4][rb + 8];
      }
      #pragma unroll
      for (int nt = 0; nt < 8; nt++){
        int nb = warpN * 64 + nt * 8 + (lane >> 2);
        bf[nt][0] = Bs[kr    ][nb];
        bf[nt][1] = Bs[kr + 4][nb];
      }
      #pragma unroll
      for (int mt = 0; mt < 2; mt++)
        #pragma unroll
        for (int nt = 0; nt < 8; nt++)
          mma_tf32(acc[mt][nt], af[mt], bf[nt]);
    }
    __syncthreads();
  }
  #pragma unroll
  for (int mt = 0; mt < 2; mt++){
    #pragma unroll
    for (int ii = 0; ii < 2; ii++){
      int o = m0 + warpM * 32 + mt * 16 + (lane >> 2) + ii * 8;
      float bi = bias[o];
      int h = o >> 6, dd = o & 63;
      #pragma unroll
      for (int nt = 0; nt < 8; nt++){
        #pragma unroll
        for (int jj = 0; jj < 2; jj++){
          int n = n0 + warpN * 64 + nt * 8 + (lane & 3) * 2 + jj;
          float v = acc[mt][nt][ii * 2 + jj] + bi;
          if (dd < 32) g_wq[((b * 8 + h) * 1024 + n) * 32 + dd] = v;
          else         g_wkt[((b * 8 + h) * 32 + (dd - 32)) * 1024 + n] = v;
        }
      }
    }
  }
}

// ---------------- K4a: window dots (tf32) + rowmax reduce ----------------
__global__ __launch_bounds__(256) void k_dots(){
  __shared__ uint32_t As[32][132];
  __shared__ uint32_t Bs[32][132];
  int tid = threadIdx.x;
  int lane = tid & 31, warp = tid >> 5;
  int warpM = warp >> 1, warpN = warp & 1;
  int bh = blockIdx.z;
  int m0 = blockIdx.y * 128, n0 = blockIdx.x * 128;
  const float* Ap = g_wq + bh * 32768;
  const float* Bp = g_wkt + bh * 32768;

  int ar = tid >> 1, ac = (tid & 1) * 16;
  #pragma unroll
  for (int i = 0; i < 16; i += 4){
    float4 v = *(const float4*)(Ap + (m0 + ar) * 32 + ac + i);
    As[ac+i+0][ar]=f2tf32(v.x); As[ac+i+1][ar]=f2tf32(v.y);
    As[ac+i+2][ar]=f2tf32(v.z); As[ac+i+3][ar]=f2tf32(v.w);
  }
  int br = tid >> 3, bc = (tid & 7) * 16;
  #pragma unroll
  for (int i = 0; i < 16; i += 4){
    float4 v = *(const float4*)(Bp + br * 1024 + n0 + bc + i);
    Bs[br][bc+i+0]=f2tf32(v.x); Bs[br][bc+i+1]=f2tf32(v.y);
    Bs[br][bc+i+2]=f2tf32(v.z); Bs[br][bc+i+3]=f2tf32(v.w);
  }
  __syncthreads();

  float acc[2][8][4];
  #pragma unroll
  for (int mt = 0; mt < 2; mt++)
    #pragma unroll
    for (int nt = 0; nt < 8; nt++)
      #pragma unroll
      for (int i = 0; i < 4; i++) acc[mt][nt][i] = 0.f;

  #pragma unroll
  for (int kk = 0; kk < 32; kk += 8){
    uint32_t af[2][4], bf[8][2];
    int kr = kk + (lane & 3);
    #pragma unroll
    for (int mt = 0; mt < 2; mt++){
      int rb = warpM * 32 + mt * 16 + (lane >> 2);
      af[mt][0] = As[kr    ][rb];
      af[mt][1] = As[kr    ][rb + 8];
      af[mt][2] = As[kr + 4][rb];
      af[mt][3] = As[kr + 4][rb + 8];
    }
    #pragma unroll
    for (int nt = 0; nt < 8; nt++){
      int nb = warpN * 64 + nt * 8 + (lane >> 2);
      bf[nt][0] = Bs[kr    ][nb];
      bf[nt][1] = Bs[kr + 4][nb];
    }
    #pragma unroll
    for (int mt = 0; mt < 2; mt++)
      #pragma unroll
      for (int nt = 0; nt < 8; nt++)
        mma_tf32(acc[mt][nt], af[mt], bf[nt]);
  }
  float* out = g_dots + (size_t)bh * 1048576;
  unsigned* rmx = g_rmax + bh * 1024;
  #pragma unroll
  for (int mt = 0; mt < 2; mt++){
    #pragma unroll
    for (int ii = 0; ii < 2; ii++){
      int row = m0 + warpM * 32 + mt * 16 + (lane >> 2) + ii * 8;
      float rmax = -1e30f;
      #pragma unroll
      for (int nt = 0; nt < 8; nt++){
        int col = n0 + warpN * 64 + nt * 8 + (lane & 3) * 2;
        float2 v = make_float2(acc[mt][nt][ii*2] * SCALE, acc[mt][nt][ii*2+1] * SCALE);
        rmax = fmaxf(rmax, fmaxf(v.x, v.y));
        *(float2*)&out[(size_t)row * 1024 + col] = v;
      }
      // reduce across the 4 lanes sharing this row, then one atomic
      rmax = fmaxf(rmax, __shfl_xor_sync(0xffffffffu, rmax, 1));
      rmax = fmaxf(rmax, __shfl_xor_sync(0xffffffffu, rmax, 2));
      if ((lane & 3) == 0) atomicMax(&rmx[row], fenc(rmax));
    }
  }
}

// ---------------- K4c: agg GEMM (tf32) with fused softmax ----------------
// A-tile values are exponentiated on the fly; per-row sums accumulated; divide in epilogue
__global__ __launch_bounds__(256) void k_agg(){
  __shared__ uint32_t As[16][132];
  __shared__ uint32_t Bs[16][100];
  __shared__ float srow[128];
  int tid = threadIdx.x;
  int lane = tid & 31, warp = tid >> 5;
  int warpM = warp >> 1, warpN = warp & 1;
  int bh = blockIdx.z;
  int m0 = blockIdx.y * 128, n0 = blockIdx.x * 96;
  const float* Ap = g_dots + (size_t)bh * 1048576;
  const float* Bp = g_gf + (size_t)bh * 294912 + n0;

  if (tid < 128) srow[tid] = 0.f;

  float acc[2][6][4];
  #pragma unroll
  for (int mt = 0; mt < 2; mt++)
    #pragma unroll
    for (int nt = 0; nt < 6; nt++)
      #pragma unroll
      for (int i = 0; i < 4; i++) acc[mt][nt][i] = 0.f;

  int ar = tid >> 1, ac = (tid & 1) * 8;
  float rmx = fdec(g_rmax[bh * 1024 + m0 + ar]);
  float rsum = 0.f;

  for (int k0 = 0; k0 < 1024; k0 += 16){
    float4 a0 = *(const float4*)(Ap + (size_t)(m0 + ar) * 1024 + k0 + ac);
    float4 a1 = *(const float4*)(Ap + (size_t)(m0 + ar) * 1024 + k0 + ac + 4);
    float e0 = fexp(a0.x - rmx), e1 = fexp(a0.y - rmx);
    float e2 = fexp(a0.z - rmx), e3 = fexp(a0.w - rmx);
    float e4 = fexp(a1.x - rmx), e5 = fexp(a1.y - rmx);
    float e6 = fexp(a1.z - rmx), e7 = fexp(a1.w - rmx);
    rsum += ((e0 + e1) + (e2 + e3)) + ((e4 + e5) + (e6 + e7));
    As[ac+0][ar]=f2tf32(e0); As[ac+1][ar]=f2tf32(e1);
    As[ac+2][ar]=f2tf32(e2); As[ac+3][ar]=f2tf32(e3);
    As[ac+4][ar]=f2tf32(e4); As[ac+5][ar]=f2tf32(e5);
    As[ac+6][ar]=f2tf32(e6); As[ac+7][ar]=f2tf32(e7);
    for (int l = tid; l < 1536; l += 256){
      int r = l / 96, c = l - r * 96;
      Bs[r][c] = f2tf32(Bp[(size_t)(k0 + r) * 288 + c]);
    }
    __syncthreads();
    #pragma unroll
    for (int kk = 0; kk < 16; kk += 8){
      uint32_t af[2][4], bf[6][2];
      int kr = kk + (lane & 3);
      #pragma unroll
      for (int mt = 0; mt < 2; mt++){
        int rb = warpM * 32 + mt * 16 + (lane >> 2);
        af[mt][0] = As[kr    ][rb];
        af[mt][1] = As[kr    ][rb + 8];
        af[mt][2] = As[kr + 4][rb];
        af[mt][3] = As[kr + 4][rb + 8];
      }
      #pragma unroll
      for (int nt = 0; nt < 6; nt++){
        int nb = warpN * 48 + nt * 8 + (lane >> 2);
        bf[nt][0] = Bs[kr    ][nb];
        bf[nt][1] = Bs[kr + 4][nb];
      }
      #pragma unroll
      for (int mt = 0; mt < 2; mt++)
        #pragma unroll
        for (int nt = 0; nt < 6; nt++)
          mma_tf32(acc[mt][nt], af[mt], bf[nt]);
    }
    __syncthreads();
  }
  atomicAdd(&srow[ar], rsum);
  __syncthreads();

  float* out = g_agg + (size_t)bh * 294912;
  #pragma unroll
  for (int mt = 0; mt < 2; mt++){
    #pragma unroll
    for (int ii = 0; ii < 2; ii++){
      int rl = warpM * 32 + mt * 16 + (lane >> 2) + ii * 8;
      float inv = 1.f / srow[rl];
      int row = m0 + rl;
      #pragma unroll
      for (int nt = 0; nt < 6; nt++){
        int col = n0 + warpN * 48 + nt * 8 + (lane & 3) * 2;
        out[(size_t)row * 288 + col    ] = acc[mt][nt][ii * 2    ] * inv;
        out[(size_t)row * 288 + col + 1] = acc[mt][nt][ii * 2 + 1] * inv;
      }
    }
  }
}

// ---------------- K5: output projection (tf32) M=256, K=256, N=147456 -------------------
__global__ __launch_bounds__(256) void k_out(const float* __restrict__ W,
                                             const float* __restrict__ bias,
                                             float* __restrict__ out){
  __shared__ uint32_t As[16][132];
  __shared__ uint32_t Bs[16][132];
  int tid = threadIdx.x;
  int lane = tid & 31, warp = tid >> 5;
  int warpM = warp >> 1, warpN = warp & 1;
  int n0 = blockIdx.x * 128, m0 = blockIdx.y * 128;
  int b = n0 / PIX;
  int pix0 = n0 - b * PIX;

  int nb = tid & 127;
  int kh = tid >> 7;
  int pix = pix0 + nb;
  int y = pix / HWDIM, xc = pix - y * HWDIM;
  int g = (y / 3) * 32 + xc / 3;
  int win = (y % 3) * 3 + (xc % 3);
  size_t colbase = (size_t)b * 2359296 + (size_t)g * 288 + win * 32;

  int ar = tid >> 1, ac = (tid & 1) * 8;

  float acc[2][8][4];
  #pragma unroll
  for (int mt = 0; mt < 2; mt++)
    #pragma unroll
    for (int nt = 0; nt < 8; nt++)
      #pragma unroll
      for (int i = 0; i < 4; i++) acc[mt][nt][i] = 0.f;

  for (int k0 = 0; k0 < 256; k0 += 16){
    float4 a0 = *(const float4*)(W + (m0 + ar) * 256 + k0 + ac);
    float4 a1 = *(const float4*)(W + (m0 + ar) * 256 + k0 + ac + 4);
    As[ac+0][ar]=f2tf32(a0.x); As[ac+1][ar]=f2tf32(a0.y);
    As[ac+2][ar]=f2tf32(a0.z); As[ac+3][ar]=f2tf32(a0.w);
    As[ac+4][ar]=f2tf32(a1.x); As[ac+5][ar]=f2tf32(a1.y);
    As[ac+6][ar]=f2tf32(a1.z); As[ac+7][ar]=f2tf32(a1.w);
    int h = k0 >> 5, dbase = (k0 & 31) + kh * 8;
    const float* bsrc = g_agg + colbase + (size_t)h * 294912 + dbase;
    float4 v0 = *(const float4*)(bsrc + 0);
    float4 v1 = *(const float4*)(bsrc + 4);
    int kb = kh * 8;
    Bs[kb+0][nb]=f2tf32(v0.x); Bs[kb+1][nb]=f2tf32(v0.y);
    Bs[kb+2][nb]=f2tf32(v0.z); Bs[kb+3][nb]=f2tf32(v0.w);
    Bs[kb+4][nb]=f2tf32(v1.x); Bs[kb+5][nb]=f2tf32(v1.y);
    Bs[kb+6][nb]=f2tf32(v1.z); Bs[kb+7][nb]=f2tf32(v1.w);
    __syncthreads();
    #pragma unroll
    for (int kk = 0; kk < 16; kk += 8){
      uint32_t af[2][4], bf[8][2];
      int kr = kk + (lane & 3);
      #pragma unroll
      for (int mt = 0; mt < 2; mt++){
        int rb = warpM * 32 + mt * 16 + (lane >> 2);
        af[mt][0] = As[kr    ][rb];
        af[mt][1] = As[kr    ][rb + 8];
        af[mt][2] = As[kr + 4][rb];
        af[mt][3] = As[kr + 4][rb + 8];
      }
      #pragma unroll
      for (int nt = 0; nt < 8; nt++){
        int nbc = warpN * 64 + nt * 8 + (lane >> 2);
        bf[nt][0] = Bs[kr    ][nbc];
        bf[nt][1] = Bs[kr + 4][nbc];
      }
      #pragma unroll
      for (int mt = 0; mt < 2; mt++)
        #pragma unroll
        for (int nt = 0; nt < 8; nt++)
          mma_tf32(acc[mt][nt], af[mt], bf[nt]);
    }
    __syncthreads();
  }
  float* op = out + ((size_t)b * 256) * PIX + pix0;
  #pragma unroll
  for (int mt = 0; mt < 2; mt++){
    #pragma unroll
    for (int ii = 0; ii < 2; ii++){
      int o = m0 + warpM * 32 + mt * 16 + (lane >> 2) + ii * 8;
      float bi = bias[o];
      #pragma unroll
      for (int nt = 0; nt < 8; nt++){
        int col = warpN * 64 + nt * 8 + (lane & 3) * 2;
        float2 v = make_float2(acc[mt][nt][ii*2] + bi, acc[mt][nt][ii*2+1] + bi);
        *(float2*)&op[(size_t)o * PIX + col] = v;
      }
    }
  }
}

// ---------------- launch ----------------
extern "C" void kernel_launch(void* const* d_in, const int* in_sizes, int n_in,
                              void* d_out, int out_size){
  const float* x      = (const float*)d_in[0];
  const float* w_qkv  = (const float*)d_in[1];
  const float* gtok   = (const float*)d_in[2];
  const float* gamma  = (const float*)d_in[3];
  const float* beta   = (const float*)d_in[4];
  const float* w_qk   = (const float*)d_in[5];
  const float* b_qk   = (const float*)d_in[6];
  const float* w_out  = (const float*)d_in[7];
  const float* b_out  = (const float*)d_in[8];
  float* out = (float*)d_out;

  k_zero <<<128, 256>>>();
  k_tok  <<<3, 256>>>(w_qkv, gtok);
  k_qkv  <<<dim3(1152, 6), 256>>>(w_qkv, x);
  k_attn1<<<16384, 256>>>(gamma, beta);
  k_qk   <<<dim3(8, 4, 16), 256>>>(w_qk, b_qk);
  k_dots <<<dim3(8, 8, 128), 256>>>();
  k_agg  <<<dim3(3, 8, 128), 256>>>();
  k_out  <<<dim3(1152, 2), 256>>>(w_out, b_out, out);
}